// round 1
// baseline (speedup 1.0000x reference)
#include <cuda_runtime.h>
#include <cuda_bf16.h>
#include <math.h>

// Problem constants
#define BB 2
#define SS 2048
#define EE 1024
#define HH 16
#define DD 64
#define ROWS (BB*SS)          // 4096

// Scratch (device globals; no allocation)
__device__ float g_Q[BB*HH*SS*DD];    // [BH][S][D]
__device__ float g_K[BB*HH*SS*DD];
__device__ float g_V[BB*HH*SS*DD];
__device__ float g_ctx[ROWS*EE];      // [row][E]

// ---------------------------------------------------------------------------
// Tiled fp32 GEMM: C[M=4096, N] = A[4096,1024] @ W[1024,N] (+bias)
// 128x128 block tile, K-step 8, 256 threads, 8x8 per-thread micro-tile.
// QKV=true: scatter epilogue into g_Q/g_K/g_V with [B,H,S,D] layout.
// ---------------------------------------------------------------------------
template<int N, bool QKV>
__global__ __launch_bounds__(256)
void gemm_kernel(const float* __restrict__ A, const float* __restrict__ W,
                 const float* __restrict__ bias, float* __restrict__ C)
{
    const int K = 1024;
    __shared__ float As[8*128];
    __shared__ float Bs[8*128];

    const int tid  = threadIdx.x;
    const int m0   = blockIdx.y * 128;
    const int n0   = blockIdx.x * 128;
    const int trow = tid >> 4;      // 0..15
    const int tcol = tid & 15;      // 0..15

    float acc[8][8];
    #pragma unroll
    for (int i = 0; i < 8; i++)
        #pragma unroll
        for (int j = 0; j < 8; j++) acc[i][j] = 0.0f;

    const int aRow = tid >> 1;          // 0..127
    const int aCol = (tid & 1) * 4;     // 0 or 4
    const int bRow = tid >> 5;          // 0..7
    const int bCol = (tid & 31) * 4;    // 0..124

    const float* Aptr = A + (size_t)(m0 + aRow) * K + aCol;
    const float* Wptr = W + (size_t)bRow * N + n0 + bCol;

    for (int k0 = 0; k0 < K; k0 += 8) {
        float4 a4 = *(const float4*)(Aptr + k0);
        float4 b4 = *(const float4*)(Wptr + (size_t)k0 * N);
        As[(aCol+0)*128 + aRow] = a4.x;
        As[(aCol+1)*128 + aRow] = a4.y;
        As[(aCol+2)*128 + aRow] = a4.z;
        As[(aCol+3)*128 + aRow] = a4.w;
        *(float4*)&Bs[bRow*128 + bCol] = b4;
        __syncthreads();

        #pragma unroll
        for (int kk = 0; kk < 8; kk++) {
            float ar[8], br[8];
            float4 t0 = *(const float4*)&As[kk*128 + trow*8];
            float4 t1 = *(const float4*)&As[kk*128 + trow*8 + 4];
            ar[0]=t0.x; ar[1]=t0.y; ar[2]=t0.z; ar[3]=t0.w;
            ar[4]=t1.x; ar[5]=t1.y; ar[6]=t1.z; ar[7]=t1.w;
            float4 u0 = *(const float4*)&Bs[kk*128 + tcol*8];
            float4 u1 = *(const float4*)&Bs[kk*128 + tcol*8 + 4];
            br[0]=u0.x; br[1]=u0.y; br[2]=u0.z; br[3]=u0.w;
            br[4]=u1.x; br[5]=u1.y; br[6]=u1.z; br[7]=u1.w;
            #pragma unroll
            for (int i = 0; i < 8; i++)
                #pragma unroll
                for (int j = 0; j < 8; j++)
                    acc[i][j] = fmaf(ar[i], br[j], acc[i][j]);
        }
        __syncthreads();
    }

    // Epilogue
    #pragma unroll
    for (int i = 0; i < 8; i++) {
        const int row = m0 + trow*8 + i;
        #pragma unroll
        for (int j = 0; j < 8; j++) {
            const int col = n0 + tcol*8 + j;
            float v = acc[i][j] + bias[col];
            if (QKV) {
                const int b = row >> 11;          // /2048
                const int s = row & 2047;
                const int which = col >> 10;      // 0=Q,1=K,2=V
                const int h = (col >> 6) & 15;
                const int d = col & 63;
                const size_t o = ((size_t)((b*HH + h)*SS + s))*DD + d;
                float* dst = (which == 0) ? g_Q : (which == 1) ? g_K : g_V;
                dst[o] = v;
            } else {
                C[(size_t)row * N + col] = v;
            }
        }
    }
}

// ---------------------------------------------------------------------------
// Flash attention (fp32): grid (S/64, B*H); block 256 threads.
// 64 query rows per block, 32-key tiles, online softmax.
// Thread (ty,tx): rows {16*i+ty}, score-cols {16*k+tx}, out-cols {16*k+tx}.
// ---------------------------------------------------------------------------
__global__ __launch_bounds__(256)
void attn_kernel(const int* __restrict__ mask)
{
    __shared__ float Qs[64*64];    // [r][d] stride 64
    __shared__ float KP[64*33];    // K tile [c][d] stride 65 (32*65=2080 floats), aliased by P [r][key] stride 33 (2112 floats)
    __shared__ float Vs[32*64];    // [key][d] stride 64

    const int bh = blockIdx.y;           // 0..31
    const int b  = bh >> 4;
    const int h  = bh & 15;
    const int q0 = blockIdx.x * 64;
    const int tid = threadIdx.x;
    const int ty = tid >> 4;             // 0..15
    const int tx = tid & 15;             // 0..15

    const float* Qg = g_Q + ((size_t)bh * SS + q0) * DD;
    const float* Kg0 = g_K + (size_t)bh * SS * DD;
    const float* Vg0 = g_V + (size_t)bh * SS * DD;
    const int* maskb = mask + b * SS;

    // Load Q tile (64x64, contiguous)
    for (int idx = tid; idx < 64*64; idx += 256)
        Qs[idx] = Qg[idx];

    float m_prev[4], l_prev[4];
    float Oacc[4][4];
    #pragma unroll
    for (int i = 0; i < 4; i++) {
        m_prev[i] = -INFINITY; l_prev[i] = 0.0f;
        #pragma unroll
        for (int k = 0; k < 4; k++) Oacc[i][k] = 0.0f;
    }

    const float scale = 0.125f;   // 1/sqrt(64)

    for (int kt = 0; kt < SS/32; kt++) {
        __syncthreads();   // previous iter's P/V readers are done
        // Load K tile -> KP (stride 65), V tile -> Vs (stride 64)
        const float* Kg = Kg0 + (size_t)(kt*32) * DD;
        const float* Vg = Vg0 + (size_t)(kt*32) * DD;
        for (int idx = tid; idx < 32*64; idx += 256) {
            const int c = idx >> 6, d = idx & 63;
            KP[c*65 + d] = Kg[idx];
            Vs[idx]      = Vg[idx];
        }
        __syncthreads();

        // scores: acc[i][k] = Q rows {16i+ty} . K cols {16k+tx}
        float acc[4][2];
        #pragma unroll
        for (int i = 0; i < 4; i++) { acc[i][0] = 0.0f; acc[i][1] = 0.0f; }
        #pragma unroll 8
        for (int d = 0; d < 64; d++) {
            float qv[4], kv[2];
            #pragma unroll
            for (int i = 0; i < 4; i++) qv[i] = Qs[(16*i + ty)*64 + d];
            kv[0] = KP[(tx)*65 + d];
            kv[1] = KP[(16 + tx)*65 + d];
            #pragma unroll
            for (int i = 0; i < 4; i++) {
                acc[i][0] = fmaf(qv[i], kv[0], acc[i][0]);
                acc[i][1] = fmaf(qv[i], kv[1], acc[i][1]);
            }
        }

        // mask + scale
        const int mv0 = maskb[kt*32 + tx];
        const int mv1 = maskb[kt*32 + 16 + tx];
        #pragma unroll
        for (int i = 0; i < 4; i++) {
            acc[i][0] = (mv0 == 0) ? -INFINITY : acc[i][0] * scale;
            acc[i][1] = (mv1 == 0) ? -INFINITY : acc[i][1] * scale;
        }

        // online softmax (per-row, reduce across 16 lanes of same ty)
        float mnew[4], alpha[4], p[4][2];
        #pragma unroll
        for (int i = 0; i < 4; i++) {
            float mx = fmaxf(acc[i][0], acc[i][1]);
            #pragma unroll
            for (int off = 8; off > 0; off >>= 1)
                mx = fmaxf(mx, __shfl_xor_sync(0xffffffffu, mx, off, 16));
            mnew[i] = fmaxf(m_prev[i], mx);
            alpha[i] = __expf(m_prev[i] - mnew[i]);
            p[i][0] = __expf(acc[i][0] - mnew[i]);
            p[i][1] = __expf(acc[i][1] - mnew[i]);
            float ls = p[i][0] + p[i][1];
            #pragma unroll
            for (int off = 8; off > 0; off >>= 1)
                ls += __shfl_xor_sync(0xffffffffu, ls, off, 16);
            l_prev[i] = l_prev[i] * alpha[i] + ls;
            m_prev[i] = mnew[i];
        }

        __syncthreads();    // done reading KP as K

        // store P into KP region (stride 33)
        #pragma unroll
        for (int i = 0; i < 4; i++) {
            KP[(16*i + ty)*33 + tx]      = p[i][0];
            KP[(16*i + ty)*33 + 16 + tx] = p[i][1];
        }
        __syncthreads();

        // O update: Oacc[i][k] = Oacc*alpha + sum_key P[r][key]*V[key][dc]
        #pragma unroll
        for (int i = 0; i < 4; i++)
            #pragma unroll
            for (int k = 0; k < 4; k++) Oacc[i][k] *= alpha[i];

        #pragma unroll 4
        for (int key = 0; key < 32; key++) {
            float pv[4], vv[4];
            #pragma unroll
            for (int i = 0; i < 4; i++) pv[i] = KP[(16*i + ty)*33 + key];
            #pragma unroll
            for (int k = 0; k < 4; k++) vv[k] = Vs[key*64 + 16*k + tx];
            #pragma unroll
            for (int i = 0; i < 4; i++)
                #pragma unroll
                for (int k = 0; k < 4; k++)
                    Oacc[i][k] = fmaf(pv[i], vv[k], Oacc[i][k]);
        }
    }

    // Epilogue: ctx[(b*S + q)*E + h*64 + dc] = Oacc / l
    #pragma unroll
    for (int i = 0; i < 4; i++) {
        const float inv_l = 1.0f / l_prev[i];
        const int q = q0 + 16*i + ty;
        float* dst = g_ctx + (size_t)(b*SS + q)*EE + h*DD;
        #pragma unroll
        for (int k = 0; k < 4; k++)
            dst[16*k + tx] = Oacc[i][k] * inv_l;
    }
}

// ---------------------------------------------------------------------------
extern "C" void kernel_launch(void* const* d_in, const int* in_sizes, int n_in,
                              void* d_out, int out_size)
{
    const float* x    = (const float*)d_in[0];
    const int*   mask = (const int*)  d_in[1];
    const float* Wqkv = (const float*)d_in[2];
    const float* bqkv = (const float*)d_in[3];
    const float* Wout = (const float*)d_in[4];
    const float* bout = (const float*)d_in[5];
    float* out = (float*)d_out;

    // 1) QKV projection + scatter to [B,H,S,D]
    gemm_kernel<3*EE, true><<<dim3(3*EE/128, ROWS/128), 256>>>(x, Wqkv, bqkv, nullptr);

    // 2) attention
    attn_kernel<<<dim3(SS/64, BB*HH), 256>>>(mask);

    // 3) output projection
    float* ctx_ptr;
    cudaGetSymbolAddress((void**)&ctx_ptr, g_ctx);
    gemm_kernel<EE, false><<<dim3(EE/128, ROWS/128), 256>>>(ctx_ptr, Wout, bout, out);
}

// round 3
// speedup vs baseline: 1.3943x; 1.3943x over previous
#include <cuda_runtime.h>
#include <cuda_bf16.h>
#include <math.h>
#include <stdint.h>

#define BB 2
#define SS 2048
#define EE 1024
#define HH 16
#define DD 64
#define ROWS (BB*SS)     // 4096
#define KK 1024

// ---------------- scratch (device globals; no allocation) -------------------
__device__ float g_Q[BB*HH*SS*DD];
__device__ float g_K[BB*HH*SS*DD];
__device__ float g_V[BB*HH*SS*DD];
__device__ float g_ctx[ROWS*EE];
__device__ __nv_bfloat16 g_xhi[ROWS*KK], g_xlo[ROWS*KK];
__device__ __nv_bfloat16 g_cthi[ROWS*KK], g_ctlo[ROWS*KK];
__device__ __nv_bfloat16 g_wqhi[3*EE*KK], g_wqlo[3*EE*KK];   // [N=3072][K]
__device__ __nv_bfloat16 g_wohi[EE*KK],  g_wolo[EE*KK];      // [N=1024][K]

// ---------------- helpers ---------------------------------------------------
__device__ __forceinline__ uint32_t smem_u32(const void* p){
    uint32_t a;
    asm("{ .reg .u64 t; cvta.to.shared.u64 t, %1; cvt.u32.u64 %0, t; }" : "=r"(a) : "l"(p));
    return a;
}
#define SW128(o) ((o) ^ (((o) >> 3) & 0x70))

__device__ __forceinline__ void ldsm4(uint32_t addr, uint32_t& r0, uint32_t& r1,
                                      uint32_t& r2, uint32_t& r3){
    asm volatile("ldmatrix.sync.aligned.m8n8.x4.shared.b16 {%0,%1,%2,%3}, [%4];"
        : "=r"(r0), "=r"(r1), "=r"(r2), "=r"(r3) : "r"(addr));
}
__device__ __forceinline__ void mma_bf16(float* c, const uint32_t* a, const uint32_t* b){
    asm volatile("mma.sync.aligned.m16n8k16.row.col.f32.bf16.bf16.f32 "
        "{%0,%1,%2,%3}, {%4,%5,%6,%7}, {%8,%9}, {%0,%1,%2,%3};"
        : "+f"(c[0]), "+f"(c[1]), "+f"(c[2]), "+f"(c[3])
        : "r"(a[0]), "r"(a[1]), "r"(a[2]), "r"(a[3]), "r"(b[0]), "r"(b[1]));
}

// ---------------------------------------------------------------------------
// Prep: fp32 -> (hi, lo) bf16 split
// ---------------------------------------------------------------------------
__global__ __launch_bounds__(256)
void split_kernel(const float* __restrict__ src, __nv_bfloat16* __restrict__ hi,
                  __nv_bfloat16* __restrict__ lo, int n4)
{
    int i = blockIdx.x * 256 + threadIdx.x;
    if (i >= n4) return;
    float4 v = ((const float4*)src)[i];
    __nv_bfloat16 h[4], l[4];
    float f[4] = {v.x, v.y, v.z, v.w};
    #pragma unroll
    for (int j = 0; j < 4; j++) {
        h[j] = __float2bfloat16(f[j]);
        l[j] = __float2bfloat16(f[j] - __bfloat162float(h[j]));
    }
    ((__nv_bfloat162*)hi)[i*2+0] = __nv_bfloat162(h[0], h[1]);
    ((__nv_bfloat162*)hi)[i*2+1] = __nv_bfloat162(h[2], h[3]);
    ((__nv_bfloat162*)lo)[i*2+0] = __nv_bfloat162(l[0], l[1]);
    ((__nv_bfloat162*)lo)[i*2+1] = __nv_bfloat162(l[2], l[3]);
}

// Prep: W[K,N] fp32 -> WT[N,K] bf16 hi/lo (tiled transpose)
__global__ __launch_bounds__(256)
void transpose_split_kernel(const float* __restrict__ W, __nv_bfloat16* __restrict__ Thi,
                            __nv_bfloat16* __restrict__ Tlo, int K, int N)
{
    __shared__ float tile[32][33];
    const int n0 = blockIdx.x * 32, k0 = blockIdx.y * 32;
    const int tx = threadIdx.x & 31, ty = threadIdx.x >> 5;   // 32 x 8
    #pragma unroll
    for (int i = 0; i < 4; i++)
        tile[ty + 8*i][tx] = W[(size_t)(k0 + ty + 8*i) * N + n0 + tx];
    __syncthreads();
    #pragma unroll
    for (int i = 0; i < 4; i++) {
        float v = tile[tx][ty + 8*i];
        __nv_bfloat16 h = __float2bfloat16(v);
        size_t o = (size_t)(n0 + ty + 8*i) * K + k0 + tx;
        Thi[o] = h;
        Tlo[o] = __float2bfloat16(v - __bfloat162float(h));
    }
}

// ---------------------------------------------------------------------------
// HMMA bf16x3 GEMM: C[4096, N] = A[4096,1024] @ B^T[N,1024] (+bias)
// CTA 128x128, 8 warps (2m x 4n), warp tile 64x32, K-chunk 64, SW128 SMEM.
// 3 passes per k-step: Ahi*Bhi + Ahi*Blo + Alo*Bhi.
// Dynamic smem 64KB: Ahi | Alo | Bhi | Blo, each 128x64 bf16 (16KB).
// ---------------------------------------------------------------------------
template<int N, bool QKV>
__global__ __launch_bounds__(256)
void gemm_mma_kernel(const __nv_bfloat16* __restrict__ Ahi, const __nv_bfloat16* __restrict__ Alo,
                     const __nv_bfloat16* __restrict__ Bhi, const __nv_bfloat16* __restrict__ Blo,
                     const float* __restrict__ bias, float* __restrict__ C)
{
    extern __shared__ char smem[];
    const uint32_t sb = smem_u32(smem);
    const int tid = threadIdx.x;
    const int wid = tid >> 5;
    const int lane = tid & 31;
    const int m0 = blockIdx.y * 128;
    const int n0 = blockIdx.x * 128;
    const int wm = (wid & 1) * 64;       // warp M offset in tile
    const int wn = (wid >> 1) * 32;      // warp N offset in tile

    float acc[4][4][4];                  // [mfrag][nfrag][reg]
    #pragma unroll
    for (int i = 0; i < 4; i++)
        #pragma unroll
        for (int j = 0; j < 4; j++)
            #pragma unroll
            for (int r = 0; r < 4; r++) acc[i][j][r] = 0.0f;

    const int mi = lane >> 3;            // ldmatrix sub-matrix index
    const int mr = lane & 7;             // row within sub-matrix

    for (int chunk = 0; chunk < KK/64; chunk++) {
        const int k0 = chunk * 64;
        // ---- gmem -> smem (4 tiles of 128x64 bf16, SW128) ----
        #pragma unroll
        for (int t = 0; t < 4; t++) {
            const __nv_bfloat16* src = (t == 0) ? Ahi : (t == 1) ? Alo : (t == 2) ? Bhi : Blo;
            const int rbase = (t < 2) ? m0 : n0;
            char* dst = smem + t * 16384;
            #pragma unroll
            for (int i = 0; i < 4; i++) {
                const int idx = i * 256 + tid;      // 0..1023
                const int row = idx >> 3;
                const int cg  = idx & 7;
                uint4 v = *(const uint4*)(src + (size_t)(rbase + row) * KK + k0 + cg * 8);
                const uint32_t off = row * 128 + cg * 16;
                *(uint4*)(dst + SW128(off)) = v;
            }
        }
        __syncthreads();

        #pragma unroll
        for (int ks = 0; ks < 4; ks++) {
            const int kb = ks * 32;                 // byte offset of k-step
            uint32_t ah[4][4], al[4][4], bh[4][2], bl[4][2];

            // A-hi fragments: frag fm covers rows wm+fm*16..+15
            #pragma unroll
            for (int fm = 0; fm < 4; fm++) {
                uint32_t off = (uint32_t)((wm + fm*16 + (mi & 1)*8 + mr) * 128
                                          + kb + (mi >> 1)*16);
                ldsm4(sb + SW128(off), ah[fm][0], ah[fm][1], ah[fm][2], ah[fm][3]);
            }
            // B-hi fragments: x4 load covers n16 (two n8 frags)
            #pragma unroll
            for (int fn2 = 0; fn2 < 2; fn2++) {
                uint32_t off = (uint32_t)((wn + fn2*16 + (mi >> 1)*8 + mr) * 128
                                          + kb + (mi & 1)*16);
                ldsm4(sb + 32768 + SW128(off),
                      bh[fn2*2][0], bh[fn2*2][1], bh[fn2*2+1][0], bh[fn2*2+1][1]);
            }
            // pass 1: Ahi * Bhi
            #pragma unroll
            for (int fm = 0; fm < 4; fm++)
                #pragma unroll
                for (int fn = 0; fn < 4; fn++)
                    mma_bf16(acc[fm][fn], ah[fm], bh[fn]);

            // B-lo fragments
            #pragma unroll
            for (int fn2 = 0; fn2 < 2; fn2++) {
                uint32_t off = (uint32_t)((wn + fn2*16 + (mi >> 1)*8 + mr) * 128
                                          + kb + (mi & 1)*16);
                ldsm4(sb + 49152 + SW128(off),
                      bl[fn2*2][0], bl[fn2*2][1], bl[fn2*2+1][0], bl[fn2*2+1][1]);
            }
            // pass 2: Ahi * Blo
            #pragma unroll
            for (int fm = 0; fm < 4; fm++)
                #pragma unroll
                for (int fn = 0; fn < 4; fn++)
                    mma_bf16(acc[fm][fn], ah[fm], bl[fn]);

            // A-lo fragments
            #pragma unroll
            for (int fm = 0; fm < 4; fm++) {
                uint32_t off = (uint32_t)((wm + fm*16 + (mi & 1)*8 + mr) * 128
                                          + kb + (mi >> 1)*16);
                ldsm4(sb + 16384 + SW128(off), al[fm][0], al[fm][1], al[fm][2], al[fm][3]);
            }
            // pass 3: Alo * Bhi
            #pragma unroll
            for (int fm = 0; fm < 4; fm++)
                #pragma unroll
                for (int fn = 0; fn < 4; fn++)
                    mma_bf16(acc[fm][fn], al[fm], bh[fn]);
        }
        __syncthreads();
    }

    // ---- epilogue ----
    #pragma unroll
    for (int fm = 0; fm < 4; fm++) {
        #pragma unroll
        for (int fn = 0; fn < 4; fn++) {
            const int row0 = m0 + wm + fm*16 + (lane >> 2);
            const int col  = n0 + wn + fn*8 + (lane & 3)*2;
            #pragma unroll
            for (int half = 0; half < 2; half++) {
                const int row = row0 + half*8;
                #pragma unroll
                for (int e = 0; e < 2; e++) {
                    const int c = col + e;
                    float v = acc[fm][fn][half*2 + e] + bias[c];
                    if (QKV) {
                        const int b = row >> 11;
                        const int s = row & 2047;
                        const int which = c >> 10;
                        const int h = (c >> 6) & 15;
                        const int dd = c & 63;
                        float* dstp = (which == 0) ? g_Q : (which == 1) ? g_K : g_V;
                        dstp[((size_t)((b * HH + h) * SS + s)) * DD + dd] = v;
                    } else {
                        C[(size_t)row * N + c] = v;
                    }
                }
            }
        }
    }
}

// ---------------------------------------------------------------------------
// Flash attention (fp32 SIMT) — unchanged
// ---------------------------------------------------------------------------
__global__ __launch_bounds__(256)
void attn_kernel(const int* __restrict__ mask)
{
    __shared__ float Qs[64*64];
    __shared__ float KP[64*33];
    __shared__ float Vs[32*64];

    const int bh = blockIdx.y;
    const int b  = bh >> 4;
    const int h  = bh & 15;
    const int q0 = blockIdx.x * 64;
    const int tid = threadIdx.x;
    const int ty = tid >> 4;
    const int tx = tid & 15;

    const float* Qg  = g_Q + ((size_t)bh * SS + q0) * DD;
    const float* Kg0 = g_K + (size_t)bh * SS * DD;
    const float* Vg0 = g_V + (size_t)bh * SS * DD;
    const int* maskb = mask + b * SS;

    for (int idx = tid; idx < 64*64; idx += 256)
        Qs[idx] = Qg[idx];

    float m_prev[4], l_prev[4];
    float Oacc[4][4];
    #pragma unroll
    for (int i = 0; i < 4; i++) {
        m_prev[i] = -INFINITY; l_prev[i] = 0.0f;
        #pragma unroll
        for (int k = 0; k < 4; k++) Oacc[i][k] = 0.0f;
    }
    const float scale = 0.125f;

    for (int kt = 0; kt < SS/32; kt++) {
        __syncthreads();
        const float* Kg = Kg0 + (size_t)(kt*32) * DD;
        const float* Vg = Vg0 + (size_t)(kt*32) * DD;
        for (int idx = tid; idx < 32*64; idx += 256) {
            const int c = idx >> 6, d = idx & 63;
            KP[c*65 + d] = Kg[idx];
            Vs[idx]      = Vg[idx];
        }
        __syncthreads();

        float acc[4][2];
        #pragma unroll
        for (int i = 0; i < 4; i++) { acc[i][0] = 0.0f; acc[i][1] = 0.0f; }
        #pragma unroll 8
        for (int d = 0; d < 64; d++) {
            float qv[4], kv[2];
            #pragma unroll
            for (int i = 0; i < 4; i++) qv[i] = Qs[(16*i + ty)*64 + d];
            kv[0] = KP[(tx)*65 + d];
            kv[1] = KP[(16 + tx)*65 + d];
            #pragma unroll
            for (int i = 0; i < 4; i++) {
                acc[i][0] = fmaf(qv[i], kv[0], acc[i][0]);
                acc[i][1] = fmaf(qv[i], kv[1], acc[i][1]);
            }
        }

        const int mv0 = maskb[kt*32 + tx];
        const int mv1 = maskb[kt*32 + 16 + tx];
        #pragma unroll
        for (int i = 0; i < 4; i++) {
            acc[i][0] = (mv0 == 0) ? -INFINITY : acc[i][0] * scale;
            acc[i][1] = (mv1 == 0) ? -INFINITY : acc[i][1] * scale;
        }

        float mnew[4], alpha[4], p[4][2];
        #pragma unroll
        for (int i = 0; i < 4; i++) {
            float mx = fmaxf(acc[i][0], acc[i][1]);
            #pragma unroll
            for (int off = 8; off > 0; off >>= 1)
                mx = fmaxf(mx, __shfl_xor_sync(0xffffffffu, mx, off, 16));
            mnew[i] = fmaxf(m_prev[i], mx);
            alpha[i] = __expf(m_prev[i] - mnew[i]);
            p[i][0] = __expf(acc[i][0] - mnew[i]);
            p[i][1] = __expf(acc[i][1] - mnew[i]);
            float ls = p[i][0] + p[i][1];
            #pragma unroll
            for (int off = 8; off > 0; off >>= 1)
                ls += __shfl_xor_sync(0xffffffffu, ls, off, 16);
            l_prev[i] = l_prev[i] * alpha[i] + ls;
            m_prev[i] = mnew[i];
        }

        __syncthreads();
        #pragma unroll
        for (int i = 0; i < 4; i++) {
            KP[(16*i + ty)*33 + tx]      = p[i][0];
            KP[(16*i + ty)*33 + 16 + tx] = p[i][1];
        }
        __syncthreads();

        #pragma unroll
        for (int i = 0; i < 4; i++)
            #pragma unroll
            for (int k = 0; k < 4; k++) Oacc[i][k] *= alpha[i];

        #pragma unroll 4
        for (int key = 0; key < 32; key++) {
            float pv[4], vv[4];
            #pragma unroll
            for (int i = 0; i < 4; i++) pv[i] = KP[(16*i + ty)*33 + key];
            #pragma unroll
            for (int k = 0; k < 4; k++) vv[k] = Vs[key*64 + 16*k + tx];
            #pragma unroll
            for (int i = 0; i < 4; i++)
                #pragma unroll
                for (int k = 0; k < 4; k++)
                    Oacc[i][k] = fmaf(pv[i], vv[k], Oacc[i][k]);
        }
    }

    #pragma unroll
    for (int i = 0; i < 4; i++) {
        const float inv_l = 1.0f / l_prev[i];
        const int q = q0 + 16*i + ty;
        float* dst = g_ctx + (size_t)(b*SS + q)*EE + h*DD;
        #pragma unroll
        for (int k = 0; k < 4; k++)
            dst[16*k + tx] = Oacc[i][k] * inv_l;
    }
}

// ---------------------------------------------------------------------------
extern "C" void kernel_launch(void* const* d_in, const int* in_sizes, int n_in,
                              void* d_out, int out_size)
{
    const float* x    = (const float*)d_in[0];
    const int*   mask = (const int*)  d_in[1];
    const float* Wqkv = (const float*)d_in[2];
    const float* bqkv = (const float*)d_in[3];
    const float* Wout = (const float*)d_in[4];
    const float* bout = (const float*)d_in[5];
    float* out = (float*)d_out;

    __nv_bfloat16 *xhi, *xlo, *cthi, *ctlo, *wqhi, *wqlo, *wohi, *wolo;
    float* ctx;
    cudaGetSymbolAddress((void**)&xhi,  g_xhi);
    cudaGetSymbolAddress((void**)&xlo,  g_xlo);
    cudaGetSymbolAddress((void**)&cthi, g_cthi);
    cudaGetSymbolAddress((void**)&ctlo, g_ctlo);
    cudaGetSymbolAddress((void**)&wqhi, g_wqhi);
    cudaGetSymbolAddress((void**)&wqlo, g_wqlo);
    cudaGetSymbolAddress((void**)&wohi, g_wohi);
    cudaGetSymbolAddress((void**)&wolo, g_wolo);
    cudaGetSymbolAddress((void**)&ctx,  g_ctx);

    const int smem_bytes = 4 * 16384;   // 64KB
    cudaFuncSetAttribute(gemm_mma_kernel<3*EE, true>,
                         cudaFuncAttributeMaxDynamicSharedMemorySize, smem_bytes);
    cudaFuncSetAttribute(gemm_mma_kernel<EE, false>,
                         cudaFuncAttributeMaxDynamicSharedMemorySize, smem_bytes);

    // prep
    split_kernel<<<ROWS*KK/4/256, 256>>>(x, xhi, xlo, ROWS*KK/4);
    transpose_split_kernel<<<dim3(3*EE/32, KK/32), 256>>>(Wqkv, wqhi, wqlo, KK, 3*EE);
    transpose_split_kernel<<<dim3(EE/32, KK/32), 256>>>(Wout, wohi, wolo, KK, EE);

    // 1) QKV projection (HMMA) + scatter
    gemm_mma_kernel<3*EE, true><<<dim3(3*EE/128, ROWS/128), 256, smem_bytes>>>(
        xhi, xlo, wqhi, wqlo, bqkv, nullptr);

    // 2) attention (SIMT fp32)
    attn_kernel<<<dim3(SS/64, BB*HH), 256>>>(mask);

    // 3) output projection (HMMA)
    split_kernel<<<ROWS*KK/4/256, 256>>>(ctx, cthi, ctlo, ROWS*KK/4);
    gemm_mma_kernel<EE, false><<<dim3(EE/128, ROWS/128), 256, smem_bytes>>>(
        cthi, ctlo, wohi, wolo, bout, out);
}

// round 4
// speedup vs baseline: 2.7376x; 1.9633x over previous
#include <cuda_runtime.h>
#include <cuda_bf16.h>
#include <math.h>
#include <stdint.h>

#define BB 2
#define SS 2048
#define EE 1024
#define HH 16
#define DD 64
#define ROWS (BB*SS)     // 4096
#define KK 1024

// ---------------- scratch (device globals; no allocation) -------------------
__device__ float g_ctx[ROWS*EE];
__device__ __nv_bfloat16 g_Qhi[BB*HH*SS*DD], g_Qlo[BB*HH*SS*DD];   // [bh][s][d]
__device__ __nv_bfloat16 g_Khi[BB*HH*SS*DD], g_Klo[BB*HH*SS*DD];   // [bh][s][d]
__device__ __nv_bfloat16 g_Vhi[BB*HH*SS*DD], g_Vlo[BB*HH*SS*DD];   // [bh][d][s]
__device__ __nv_bfloat16 g_xhi[ROWS*KK], g_xlo[ROWS*KK];
__device__ __nv_bfloat16 g_cthi[ROWS*KK], g_ctlo[ROWS*KK];
__device__ __nv_bfloat16 g_wqhi[3*EE*KK], g_wqlo[3*EE*KK];   // [N=3072][K]
__device__ __nv_bfloat16 g_wohi[EE*KK],  g_wolo[EE*KK];      // [N=1024][K]

// ---------------- helpers ---------------------------------------------------
__device__ __forceinline__ uint32_t smem_u32(const void* p){
    uint32_t a;
    asm("{ .reg .u64 t; cvta.to.shared.u64 t, %1; cvt.u32.u64 %0, t; }" : "=r"(a) : "l"(p));
    return a;
}
#define SW128(o) ((o) ^ (((o) >> 3) & 0x70))

__device__ __forceinline__ void ldsm4(uint32_t addr, uint32_t& r0, uint32_t& r1,
                                      uint32_t& r2, uint32_t& r3){
    asm volatile("ldmatrix.sync.aligned.m8n8.x4.shared.b16 {%0,%1,%2,%3}, [%4];"
        : "=r"(r0), "=r"(r1), "=r"(r2), "=r"(r3) : "r"(addr));
}
__device__ __forceinline__ void mma_bf16(float* c, const uint32_t* a, const uint32_t* b){
    asm volatile("mma.sync.aligned.m16n8k16.row.col.f32.bf16.bf16.f32 "
        "{%0,%1,%2,%3}, {%4,%5,%6,%7}, {%8,%9}, {%0,%1,%2,%3};"
        : "+f"(c[0]), "+f"(c[1]), "+f"(c[2]), "+f"(c[3])
        : "r"(a[0]), "r"(a[1]), "r"(a[2]), "r"(a[3]), "r"(b[0]), "r"(b[1]));
}
__device__ __forceinline__ uint32_t pack_bf16(float lo, float hi){
    __nv_bfloat162 t = __floats2bfloat162_rn(lo, hi);
    return *(uint32_t*)&t;
}

// ---------------------------------------------------------------------------
// Prep kernels
// ---------------------------------------------------------------------------
__global__ __launch_bounds__(256)
void split_kernel(const float* __restrict__ src, __nv_bfloat16* __restrict__ hi,
                  __nv_bfloat16* __restrict__ lo, int n4)
{
    int i = blockIdx.x * 256 + threadIdx.x;
    if (i >= n4) return;
    float4 v = ((const float4*)src)[i];
    __nv_bfloat16 h[4], l[4];
    float f[4] = {v.x, v.y, v.z, v.w};
    #pragma unroll
    for (int j = 0; j < 4; j++) {
        h[j] = __float2bfloat16(f[j]);
        l[j] = __float2bfloat16(f[j] - __bfloat162float(h[j]));
    }
    ((__nv_bfloat162*)hi)[i*2+0] = __nv_bfloat162(h[0], h[1]);
    ((__nv_bfloat162*)hi)[i*2+1] = __nv_bfloat162(h[2], h[3]);
    ((__nv_bfloat162*)lo)[i*2+0] = __nv_bfloat162(l[0], l[1]);
    ((__nv_bfloat162*)lo)[i*2+1] = __nv_bfloat162(l[2], l[3]);
}

__global__ __launch_bounds__(256)
void transpose_split_kernel(const float* __restrict__ W, __nv_bfloat16* __restrict__ Thi,
                            __nv_bfloat16* __restrict__ Tlo, int K, int N)
{
    __shared__ float tile[32][33];
    const int n0 = blockIdx.x * 32, k0 = blockIdx.y * 32;
    const int tx = threadIdx.x & 31, ty = threadIdx.x >> 5;
    #pragma unroll
    for (int i = 0; i < 4; i++)
        tile[ty + 8*i][tx] = W[(size_t)(k0 + ty + 8*i) * N + n0 + tx];
    __syncthreads();
    #pragma unroll
    for (int i = 0; i < 4; i++) {
        float v = tile[tx][ty + 8*i];
        __nv_bfloat16 h = __float2bfloat16(v);
        size_t o = (size_t)(n0 + ty + 8*i) * K + k0 + tx;
        Thi[o] = h;
        Tlo[o] = __float2bfloat16(v - __bfloat162float(h));
    }
}

// ---------------------------------------------------------------------------
// HMMA bf16x3 GEMM (verified R3). QKV=true: split+scatter epilogue to
// Qhi/lo,Khi/lo [bh][s][d] and Vhi/lo [bh][d][s].
// ---------------------------------------------------------------------------
template<int N, bool QKV>
__global__ __launch_bounds__(256)
void gemm_mma_kernel(const __nv_bfloat16* __restrict__ Ahi, const __nv_bfloat16* __restrict__ Alo,
                     const __nv_bfloat16* __restrict__ Bhi, const __nv_bfloat16* __restrict__ Blo,
                     const float* __restrict__ bias, float* __restrict__ C)
{
    extern __shared__ char smem[];
    const uint32_t sb = smem_u32(smem);
    const int tid = threadIdx.x;
    const int wid = tid >> 5;
    const int lane = tid & 31;
    const int m0 = blockIdx.y * 128;
    const int n0 = blockIdx.x * 128;
    const int wm = (wid & 1) * 64;
    const int wn = (wid >> 1) * 32;

    float acc[4][4][4];
    #pragma unroll
    for (int i = 0; i < 4; i++)
        #pragma unroll
        for (int j = 0; j < 4; j++)
            #pragma unroll
            for (int r = 0; r < 4; r++) acc[i][j][r] = 0.0f;

    const int mi = lane >> 3;
    const int mr = lane & 7;

    for (int chunk = 0; chunk < KK/64; chunk++) {
        const int k0 = chunk * 64;
        #pragma unroll
        for (int t = 0; t < 4; t++) {
            const __nv_bfloat16* src = (t == 0) ? Ahi : (t == 1) ? Alo : (t == 2) ? Bhi : Blo;
            const int rbase = (t < 2) ? m0 : n0;
            char* dst = smem + t * 16384;
            #pragma unroll
            for (int i = 0; i < 4; i++) {
                const int idx = i * 256 + tid;
                const int row = idx >> 3;
                const int cg  = idx & 7;
                uint4 v = *(const uint4*)(src + (size_t)(rbase + row) * KK + k0 + cg * 8);
                const uint32_t off = row * 128 + cg * 16;
                *(uint4*)(dst + SW128(off)) = v;
            }
        }
        __syncthreads();

        #pragma unroll
        for (int ks = 0; ks < 4; ks++) {
            const int kb = ks * 32;
            uint32_t ah[4][4], al[4][4], bh[4][2], bl[4][2];
            #pragma unroll
            for (int fm = 0; fm < 4; fm++) {
                uint32_t off = (uint32_t)((wm + fm*16 + (mi & 1)*8 + mr) * 128
                                          + kb + (mi >> 1)*16);
                ldsm4(sb + SW128(off), ah[fm][0], ah[fm][1], ah[fm][2], ah[fm][3]);
            }
            #pragma unroll
            for (int fn2 = 0; fn2 < 2; fn2++) {
                uint32_t off = (uint32_t)((wn + fn2*16 + (mi >> 1)*8 + mr) * 128
                                          + kb + (mi & 1)*16);
                ldsm4(sb + 32768 + SW128(off),
                      bh[fn2*2][0], bh[fn2*2][1], bh[fn2*2+1][0], bh[fn2*2+1][1]);
            }
            #pragma unroll
            for (int fm = 0; fm < 4; fm++)
                #pragma unroll
                for (int fn = 0; fn < 4; fn++)
                    mma_bf16(acc[fm][fn], ah[fm], bh[fn]);
            #pragma unroll
            for (int fn2 = 0; fn2 < 2; fn2++) {
                uint32_t off = (uint32_t)((wn + fn2*16 + (mi >> 1)*8 + mr) * 128
                                          + kb + (mi & 1)*16);
                ldsm4(sb + 49152 + SW128(off),
                      bl[fn2*2][0], bl[fn2*2][1], bl[fn2*2+1][0], bl[fn2*2+1][1]);
            }
            #pragma unroll
            for (int fm = 0; fm < 4; fm++)
                #pragma unroll
                for (int fn = 0; fn < 4; fn++)
                    mma_bf16(acc[fm][fn], ah[fm], bl[fn]);
            #pragma unroll
            for (int fm = 0; fm < 4; fm++) {
                uint32_t off = (uint32_t)((wm + fm*16 + (mi & 1)*8 + mr) * 128
                                          + kb + (mi >> 1)*16);
                ldsm4(sb + 16384 + SW128(off), al[fm][0], al[fm][1], al[fm][2], al[fm][3]);
            }
            #pragma unroll
            for (int fm = 0; fm < 4; fm++)
                #pragma unroll
                for (int fn = 0; fn < 4; fn++)
                    mma_bf16(acc[fm][fn], al[fm], bh[fn]);
        }
        __syncthreads();
    }

    #pragma unroll
    for (int fm = 0; fm < 4; fm++) {
        #pragma unroll
        for (int fn = 0; fn < 4; fn++) {
            const int row0 = m0 + wm + fm*16 + (lane >> 2);
            const int col  = n0 + wn + fn*8 + (lane & 3)*2;
            #pragma unroll
            for (int half = 0; half < 2; half++) {
                const int row = row0 + half*8;
                #pragma unroll
                for (int e = 0; e < 2; e++) {
                    const int c = col + e;
                    float v = acc[fm][fn][half*2 + e] + bias[c];
                    if (QKV) {
                        const int b = row >> 11;
                        const int s = row & 2047;
                        const int which = c >> 10;
                        const int h = (c >> 6) & 15;
                        const int dd = c & 63;
                        __nv_bfloat16 vh = __float2bfloat16(v);
                        __nv_bfloat16 vl = __float2bfloat16(v - __bfloat162float(vh));
                        if (which == 2) {
                            const size_t o = ((size_t)((b*HH + h)*DD + dd))*SS + s;
                            g_Vhi[o] = vh; g_Vlo[o] = vl;
                        } else {
                            const size_t o = ((size_t)((b*HH + h)*SS + s))*DD + dd;
                            if (which == 0) { g_Qhi[o] = vh; g_Qlo[o] = vl; }
                            else            { g_Khi[o] = vh; g_Klo[o] = vl; }
                        }
                    } else {
                        C[(size_t)row * N + c] = v;
                    }
                }
            }
        }
    }
}

// ---------------------------------------------------------------------------
// HMMA bf16x3 flash attention.
// Grid (S/128, BH). 8 warps, each owns m16 q-rows. 64-key iterations.
// smem: [0,8K) Khi | [8K,16K) Klo | [16K,24K) Vhi^T | [24K,32K) Vlo^T | mask bias
// (Q phase reuses [0,32K) for Qhi/Qlo staging.)
// ---------------------------------------------------------------------------
__global__ __launch_bounds__(256)
void attn_mma_kernel(const int* __restrict__ mask)
{
    __shared__ __align__(128) char smem[32768 + 256];
    const uint32_t sb = smem_u32(smem);
    float* mbias = (float*)(smem + 32768);

    const int bh = blockIdx.y;
    const int b  = bh >> 4;
    const int hh = bh & 15;
    const int q0 = blockIdx.x * 128;
    const int tid = threadIdx.x, wid = tid >> 5, lane = tid & 31;
    const int mi = lane >> 3, mr = lane & 7;

    // ---- stage Q tile (128x64 hi/lo) and pull A-fragments into registers
    {
        const __nv_bfloat16* qh = g_Qhi + ((size_t)bh*SS + q0)*DD;
        const __nv_bfloat16* ql = g_Qlo + ((size_t)bh*SS + q0)*DD;
        #pragma unroll
        for (int i = 0; i < 4; i++) {
            int idx = i*256 + tid;
            int row = idx >> 3, cg = idx & 7;
            uint32_t off = row*128 + cg*16;
            *(uint4*)(smem + SW128(off))         = *(const uint4*)(qh + (size_t)row*DD + cg*8);
            *(uint4*)(smem + 16384 + SW128(off)) = *(const uint4*)(ql + (size_t)row*DD + cg*8);
        }
    }
    __syncthreads();
    uint32_t qh[4][4], ql[4][4];
    #pragma unroll
    for (int kf = 0; kf < 4; kf++) {
        uint32_t off = (uint32_t)((wid*16 + (mi & 1)*8 + mr)*128 + kf*32 + (mi >> 1)*16);
        ldsm4(sb + SW128(off),         qh[kf][0], qh[kf][1], qh[kf][2], qh[kf][3]);
        ldsm4(sb + 16384 + SW128(off), ql[kf][0], ql[kf][1], ql[kf][2], ql[kf][3]);
    }
    __syncthreads();

    float O[8][4];
    #pragma unroll
    for (int fn = 0; fn < 8; fn++)
        #pragma unroll
        for (int r = 0; r < 4; r++) O[fn][r] = 0.0f;
    float m_prev[2] = {-1e30f, -1e30f}, l_prev[2] = {0.0f, 0.0f};

    const __nv_bfloat16* Khi0 = g_Khi + (size_t)bh*SS*DD;
    const __nv_bfloat16* Klo0 = g_Klo + (size_t)bh*SS*DD;
    const __nv_bfloat16* Vhi0 = g_Vhi + (size_t)bh*DD*SS;
    const __nv_bfloat16* Vlo0 = g_Vlo + (size_t)bh*DD*SS;

    for (int kt = 0; kt < SS/64; kt++) {
        const int k0 = kt*64;
        // ---- load K (rows=key, cols=d) and V^T (rows=d, cols=key) hi/lo tiles
        #pragma unroll
        for (int i = 0; i < 2; i++) {
            int idx = i*256 + tid;          // 0..511 = 64 rows x 8 groups
            int row = idx >> 3, cg = idx & 7;
            uint32_t off = row*128 + cg*16;
            uint32_t swo = SW128(off);
            *(uint4*)(smem + swo)         = *(const uint4*)(Khi0 + (size_t)(k0+row)*DD + cg*8);
            *(uint4*)(smem + 8192 + swo)  = *(const uint4*)(Klo0 + (size_t)(k0+row)*DD + cg*8);
            *(uint4*)(smem + 16384 + swo) = *(const uint4*)(Vhi0 + (size_t)row*SS + k0 + cg*8);
            *(uint4*)(smem + 24576 + swo) = *(const uint4*)(Vlo0 + (size_t)row*SS + k0 + cg*8);
        }
        if (tid < 64) mbias[tid] = mask[b*SS + k0 + tid] ? 0.0f : -1e30f;
        __syncthreads();

        // ---- S = Q K^T (3-pass split)
        float S[8][4];
        #pragma unroll
        for (int fn = 0; fn < 8; fn++)
            #pragma unroll
            for (int r = 0; r < 4; r++) S[fn][r] = 0.0f;

        #pragma unroll
        for (int kf = 0; kf < 4; kf++) {
            uint32_t kh[8][2], kl[8][2];
            #pragma unroll
            for (int fn2 = 0; fn2 < 4; fn2++) {
                uint32_t off = (uint32_t)((fn2*16 + (mi >> 1)*8 + mr)*128 + kf*32 + (mi & 1)*16);
                ldsm4(sb + SW128(off),
                      kh[fn2*2][0], kh[fn2*2][1], kh[fn2*2+1][0], kh[fn2*2+1][1]);
                ldsm4(sb + 8192 + SW128(off),
                      kl[fn2*2][0], kl[fn2*2][1], kl[fn2*2+1][0], kl[fn2*2+1][1]);
            }
            #pragma unroll
            for (int fn = 0; fn < 8; fn++) {
                mma_bf16(S[fn], qh[kf], kh[fn]);
                mma_bf16(S[fn], qh[kf], kl[fn]);
                mma_bf16(S[fn], ql[kf], kh[fn]);
            }
        }

        // ---- mask + scale
        #pragma unroll
        for (int fn = 0; fn < 8; fn++) {
            const int c0 = fn*8 + (lane & 3)*2;
            const float b0 = mbias[c0], b1 = mbias[c0+1];
            S[fn][0] = S[fn][0]*0.125f + b0;
            S[fn][1] = S[fn][1]*0.125f + b1;
            S[fn][2] = S[fn][2]*0.125f + b0;
            S[fn][3] = S[fn][3]*0.125f + b1;
        }

        // ---- online softmax (rows: h=0 -> lane>>2, h=1 -> +8)
        float mnew[2], alpha[2];
        #pragma unroll
        for (int h = 0; h < 2; h++) {
            float mx = -1e30f;
            #pragma unroll
            for (int fn = 0; fn < 8; fn++)
                mx = fmaxf(mx, fmaxf(S[fn][h*2], S[fn][h*2+1]));
            mx = fmaxf(mx, __shfl_xor_sync(0xffffffffu, mx, 1));
            mx = fmaxf(mx, __shfl_xor_sync(0xffffffffu, mx, 2));
            mnew[h] = fmaxf(m_prev[h], mx);
            alpha[h] = __expf(m_prev[h] - mnew[h]);
            m_prev[h] = mnew[h];
        }
        float ls[2] = {0.0f, 0.0f};
        #pragma unroll
        for (int fn = 0; fn < 8; fn++) {
            #pragma unroll
            for (int h = 0; h < 2; h++) {
                S[fn][h*2]   = __expf(S[fn][h*2]   - mnew[h]);
                S[fn][h*2+1] = __expf(S[fn][h*2+1] - mnew[h]);
                ls[h] += S[fn][h*2] + S[fn][h*2+1];
            }
        }
        #pragma unroll
        for (int h = 0; h < 2; h++) {
            ls[h] += __shfl_xor_sync(0xffffffffu, ls[h], 1);
            ls[h] += __shfl_xor_sync(0xffffffffu, ls[h], 2);
            l_prev[h] = l_prev[h]*alpha[h] + ls[h];
        }
        #pragma unroll
        for (int fn = 0; fn < 8; fn++) {
            O[fn][0] *= alpha[0]; O[fn][1] *= alpha[0];
            O[fn][2] *= alpha[1]; O[fn][3] *= alpha[1];
        }

        // ---- O += P V (3-pass split); P from S frags, V^T B-frags from smem
        #pragma unroll
        for (int kf = 0; kf < 4; kf++) {
            // A frags: pair of n8 S-frags (2kf, 2kf+1) -> m16k16
            uint32_t phi[4], plo[4];
            {
                const float* s0 = S[2*kf];
                const float* s1 = S[2*kf + 1];
                float r[8] = {s0[0], s0[1], s0[2], s0[3], s1[0], s1[1], s1[2], s1[3]};
                float h[8], l[8];
                #pragma unroll
                for (int e = 0; e < 8; e++) {
                    __nv_bfloat16 t = __float2bfloat16(r[e]);
                    h[e] = __bfloat162float(t);
                    l[e] = r[e] - h[e];
                }
                phi[0] = pack_bf16(h[0], h[1]); phi[1] = pack_bf16(h[2], h[3]);
                phi[2] = pack_bf16(h[4], h[5]); phi[3] = pack_bf16(h[6], h[7]);
                plo[0] = pack_bf16(l[0], l[1]); plo[1] = pack_bf16(l[2], l[3]);
                plo[2] = pack_bf16(l[4], l[5]); plo[3] = pack_bf16(l[6], l[7]);
            }
            uint32_t vh[8][2], vl[8][2];
            #pragma unroll
            for (int fn2 = 0; fn2 < 4; fn2++) {
                uint32_t off = (uint32_t)((fn2*16 + (mi >> 1)*8 + mr)*128 + kf*32 + (mi & 1)*16);
                ldsm4(sb + 16384 + SW128(off),
                      vh[fn2*2][0], vh[fn2*2][1], vh[fn2*2+1][0], vh[fn2*2+1][1]);
                ldsm4(sb + 24576 + SW128(off),
                      vl[fn2*2][0], vl[fn2*2][1], vl[fn2*2+1][0], vl[fn2*2+1][1]);
            }
            #pragma unroll
            for (int fn = 0; fn < 8; fn++) {
                mma_bf16(O[fn], phi, vh[fn]);
                mma_bf16(O[fn], phi, vl[fn]);
                mma_bf16(O[fn], plo, vh[fn]);
            }
        }
        __syncthreads();
    }

    // ---- epilogue: ctx[(b*S+q)][hh*64 + d] = O / l
    const float inv0 = 1.0f / l_prev[0];
    const float inv1 = 1.0f / l_prev[1];
    const int row0 = q0 + wid*16 + (lane >> 2);
    #pragma unroll
    for (int fn = 0; fn < 8; fn++) {
        const int dcol = fn*8 + (lane & 3)*2;
        float* dst0 = g_ctx + (size_t)(b*SS + row0)*EE + hh*DD + dcol;
        float* dst1 = g_ctx + (size_t)(b*SS + row0 + 8)*EE + hh*DD + dcol;
        dst0[0] = O[fn][0]*inv0; dst0[1] = O[fn][1]*inv0;
        dst1[0] = O[fn][2]*inv1; dst1[1] = O[fn][3]*inv1;
    }
}

// ---------------------------------------------------------------------------
extern "C" void kernel_launch(void* const* d_in, const int* in_sizes, int n_in,
                              void* d_out, int out_size)
{
    const float* x    = (const float*)d_in[0];
    const int*   mask = (const int*)  d_in[1];
    const float* Wqkv = (const float*)d_in[2];
    const float* bqkv = (const float*)d_in[3];
    const float* Wout = (const float*)d_in[4];
    const float* bout = (const float*)d_in[5];
    float* out = (float*)d_out;

    __nv_bfloat16 *xhi, *xlo, *cthi, *ctlo, *wqhi, *wqlo, *wohi, *wolo;
    float* ctx;
    cudaGetSymbolAddress((void**)&xhi,  g_xhi);
    cudaGetSymbolAddress((void**)&xlo,  g_xlo);
    cudaGetSymbolAddress((void**)&cthi, g_cthi);
    cudaGetSymbolAddress((void**)&ctlo, g_ctlo);
    cudaGetSymbolAddress((void**)&wqhi, g_wqhi);
    cudaGetSymbolAddress((void**)&wqlo, g_wqlo);
    cudaGetSymbolAddress((void**)&wohi, g_wohi);
    cudaGetSymbolAddress((void**)&wolo, g_wolo);
    cudaGetSymbolAddress((void**)&ctx,  g_ctx);

    const int smem_bytes = 4 * 16384;   // 64KB
    cudaFuncSetAttribute(gemm_mma_kernel<3*EE, true>,
                         cudaFuncAttributeMaxDynamicSharedMemorySize, smem_bytes);
    cudaFuncSetAttribute(gemm_mma_kernel<EE, false>,
                         cudaFuncAttributeMaxDynamicSharedMemorySize, smem_bytes);

    // prep
    split_kernel<<<ROWS*KK/4/256, 256>>>(x, xhi, xlo, ROWS*KK/4);
    transpose_split_kernel<<<dim3(3*EE/32, KK/32), 256>>>(Wqkv, wqhi, wqlo, KK, 3*EE);
    transpose_split_kernel<<<dim3(EE/32, KK/32), 256>>>(Wout, wohi, wolo, KK, EE);

    // 1) QKV projection (HMMA) + split/scatter epilogue
    gemm_mma_kernel<3*EE, true><<<dim3(3*EE/128, ROWS/128), 256, smem_bytes>>>(
        xhi, xlo, wqhi, wqlo, bqkv, nullptr);

    // 2) attention (HMMA bf16x3 flash)
    attn_mma_kernel<<<dim3(SS/128, BB*HH), 256>>>(mask);

    // 3) output projection (HMMA)
    split_kernel<<<ROWS*KK/4/256, 256>>>(ctx, cthi, ctlo, ROWS*KK/4);
    gemm_mma_kernel<EE, false><<<dim3(EE/128, ROWS/128), 256, smem_bytes>>>(
        cthi, ctlo, wohi, wolo, bout, out);
}

// round 5
// speedup vs baseline: 3.5566x; 1.2992x over previous
#include <cuda_runtime.h>
#include <cuda_bf16.h>
#include <math.h>
#include <stdint.h>

#define BB 2
#define SS 2048
#define EE 1024
#define HH 16
#define DD 64
#define ROWS (BB*SS)     // 4096
#define KK 1024

// ---------------- scratch (device globals; no allocation) -------------------
__device__ __nv_bfloat16 g_Qhi[BB*HH*SS*DD], g_Qlo[BB*HH*SS*DD];   // [bh][s][d]
__device__ __nv_bfloat16 g_Khi[BB*HH*SS*DD], g_Klo[BB*HH*SS*DD];   // [bh][s][d]
__device__ __nv_bfloat16 g_Vhi[BB*HH*SS*DD], g_Vlo[BB*HH*SS*DD];   // [bh][d][s]
__device__ __nv_bfloat16 g_xhi[ROWS*KK], g_xlo[ROWS*KK];
__device__ __nv_bfloat16 g_cthi[ROWS*KK], g_ctlo[ROWS*KK];
__device__ __nv_bfloat16 g_wqhi[3*EE*KK], g_wqlo[3*EE*KK];   // [N=3072][K]
__device__ __nv_bfloat16 g_wohi[EE*KK],  g_wolo[EE*KK];      // [N=1024][K]

// ---------------- helpers ---------------------------------------------------
__device__ __forceinline__ uint32_t smem_u32(const void* p){
    uint32_t a;
    asm("{ .reg .u64 t; cvta.to.shared.u64 t, %1; cvt.u32.u64 %0, t; }" : "=r"(a) : "l"(p));
    return a;
}
#define SW128(o) ((o) ^ (((o) >> 3) & 0x70))

__device__ __forceinline__ void ldsm4(uint32_t addr, uint32_t& r0, uint32_t& r1,
                                      uint32_t& r2, uint32_t& r3){
    asm volatile("ldmatrix.sync.aligned.m8n8.x4.shared.b16 {%0,%1,%2,%3}, [%4];"
        : "=r"(r0), "=r"(r1), "=r"(r2), "=r"(r3) : "r"(addr));
}
__device__ __forceinline__ void mma_bf16(float* c, const uint32_t* a, const uint32_t* b){
    asm volatile("mma.sync.aligned.m16n8k16.row.col.f32.bf16.bf16.f32 "
        "{%0,%1,%2,%3}, {%4,%5,%6,%7}, {%8,%9}, {%0,%1,%2,%3};"
        : "+f"(c[0]), "+f"(c[1]), "+f"(c[2]), "+f"(c[3])
        : "r"(a[0]), "r"(a[1]), "r"(a[2]), "r"(a[3]), "r"(b[0]), "r"(b[1]));
}
__device__ __forceinline__ uint32_t pack_bf16(float lo, float hi){
    __nv_bfloat162 t = __floats2bfloat162_rn(lo, hi);
    return *(uint32_t*)&t;
}
__device__ __forceinline__ void cp_async16(uint32_t saddr, const void* gptr){
    asm volatile("cp.async.cg.shared.global [%0], [%1], 16;" :: "r"(saddr), "l"(gptr));
}
#define CP_COMMIT() asm volatile("cp.async.commit_group;" ::: "memory")
#define CP_WAIT(N)  asm volatile("cp.async.wait_group %0;" :: "n"(N) : "memory")

// ---------------------------------------------------------------------------
// Prep kernels
// ---------------------------------------------------------------------------
__global__ __launch_bounds__(256)
void split_kernel(const float* __restrict__ src, __nv_bfloat16* __restrict__ hi,
                  __nv_bfloat16* __restrict__ lo, int n4)
{
    int i = blockIdx.x * 256 + threadIdx.x;
    if (i >= n4) return;
    float4 v = ((const float4*)src)[i];
    __nv_bfloat16 h[4], l[4];
    float f[4] = {v.x, v.y, v.z, v.w};
    #pragma unroll
    for (int j = 0; j < 4; j++) {
        h[j] = __float2bfloat16(f[j]);
        l[j] = __float2bfloat16(f[j] - __bfloat162float(h[j]));
    }
    ((__nv_bfloat162*)hi)[i*2+0] = __nv_bfloat162(h[0], h[1]);
    ((__nv_bfloat162*)hi)[i*2+1] = __nv_bfloat162(h[2], h[3]);
    ((__nv_bfloat162*)lo)[i*2+0] = __nv_bfloat162(l[0], l[1]);
    ((__nv_bfloat162*)lo)[i*2+1] = __nv_bfloat162(l[2], l[3]);
}

__global__ __launch_bounds__(256)
void transpose_split_kernel(const float* __restrict__ W, __nv_bfloat16* __restrict__ Thi,
                            __nv_bfloat16* __restrict__ Tlo, int K, int N)
{
    __shared__ float tile[32][33];
    const int n0 = blockIdx.x * 32, k0 = blockIdx.y * 32;
    const int tx = threadIdx.x & 31, ty = threadIdx.x >> 5;
    #pragma unroll
    for (int i = 0; i < 4; i++)
        tile[ty + 8*i][tx] = W[(size_t)(k0 + ty + 8*i) * N + n0 + tx];
    __syncthreads();
    #pragma unroll
    for (int i = 0; i < 4; i++) {
        float v = tile[tx][ty + 8*i];
        __nv_bfloat16 h = __float2bfloat16(v);
        size_t o = (size_t)(n0 + ty + 8*i) * K + k0 + tx;
        Thi[o] = h;
        Tlo[o] = __float2bfloat16(v - __bfloat162float(h));
    }
}

// ---------------------------------------------------------------------------
// HMMA bf16x3 GEMM, cp.async double-buffered.
// Dyn smem: 2 stages x (Ahi|Alo|Bhi|Blo each 16KB) = 128KB.
// ---------------------------------------------------------------------------
template<int N, bool QKV>
__global__ __launch_bounds__(256)
void gemm_mma_kernel(const __nv_bfloat16* __restrict__ Ahi, const __nv_bfloat16* __restrict__ Alo,
                     const __nv_bfloat16* __restrict__ Bhi, const __nv_bfloat16* __restrict__ Blo,
                     const float* __restrict__ bias, float* __restrict__ C)
{
    extern __shared__ char smem[];
    const uint32_t sb = smem_u32(smem);
    const int tid = threadIdx.x;
    const int wid = tid >> 5;
    const int lane = tid & 31;
    const int m0 = blockIdx.y * 128;
    const int n0 = blockIdx.x * 128;
    const int wm = (wid & 1) * 64;
    const int wn = (wid >> 1) * 32;
    const int mi = lane >> 3;
    const int mr = lane & 7;

    const __nv_bfloat16* srcs[4] = {Ahi, Alo, Bhi, Blo};
    const int rb[4] = {m0, m0, n0, n0};

    // issue one chunk's 4 tiles into stage st
    auto issue = [&](int chunk, int st){
        const int k0 = chunk * 64;
        const uint32_t stb = sb + st * 65536;
        #pragma unroll
        for (int t = 0; t < 4; t++) {
            #pragma unroll
            for (int i = 0; i < 4; i++) {
                const int idx = i * 256 + tid;
                const int row = idx >> 3;
                const int cg  = idx & 7;
                cp_async16(stb + t*16384 + SW128((uint32_t)(row*128 + cg*16)),
                           srcs[t] + (size_t)(rb[t] + row) * KK + k0 + cg * 8);
            }
        }
        CP_COMMIT();
    };

    float acc[4][4][4];
    #pragma unroll
    for (int i = 0; i < 4; i++)
        #pragma unroll
        for (int j = 0; j < 4; j++)
            #pragma unroll
            for (int r = 0; r < 4; r++) acc[i][j][r] = 0.0f;

    issue(0, 0);

    const int NC = KK/64;
    for (int chunk = 0; chunk < NC; chunk++) {
        const int st = chunk & 1;
        if (chunk + 1 < NC) { issue(chunk + 1, st ^ 1); CP_WAIT(1); }
        else                { CP_WAIT(0); }
        __syncthreads();

        const uint32_t stb = sb + st * 65536;
        #pragma unroll
        for (int ks = 0; ks < 4; ks++) {
            const int kb = ks * 32;
            uint32_t ah[4][4], al[4][4], bh[4][2], bl[4][2];
            #pragma unroll
            for (int fm = 0; fm < 4; fm++) {
                uint32_t off = (uint32_t)((wm + fm*16 + (mi & 1)*8 + mr) * 128
                                          + kb + (mi >> 1)*16);
                ldsm4(stb + SW128(off), ah[fm][0], ah[fm][1], ah[fm][2], ah[fm][3]);
            }
            #pragma unroll
            for (int fn2 = 0; fn2 < 2; fn2++) {
                uint32_t off = (uint32_t)((wn + fn2*16 + (mi >> 1)*8 + mr) * 128
                                          + kb + (mi & 1)*16);
                ldsm4(stb + 32768 + SW128(off),
                      bh[fn2*2][0], bh[fn2*2][1], bh[fn2*2+1][0], bh[fn2*2+1][1]);
            }
            #pragma unroll
            for (int fm = 0; fm < 4; fm++)
                #pragma unroll
                for (int fn = 0; fn < 4; fn++)
                    mma_bf16(acc[fm][fn], ah[fm], bh[fn]);
            #pragma unroll
            for (int fn2 = 0; fn2 < 2; fn2++) {
                uint32_t off = (uint32_t)((wn + fn2*16 + (mi >> 1)*8 + mr) * 128
                                          + kb + (mi & 1)*16);
                ldsm4(stb + 49152 + SW128(off),
                      bl[fn2*2][0], bl[fn2*2][1], bl[fn2*2+1][0], bl[fn2*2+1][1]);
            }
            #pragma unroll
            for (int fm = 0; fm < 4; fm++)
                #pragma unroll
                for (int fn = 0; fn < 4; fn++)
                    mma_bf16(acc[fm][fn], ah[fm], bl[fn]);
            #pragma unroll
            for (int fm = 0; fm < 4; fm++) {
                uint32_t off = (uint32_t)((wm + fm*16 + (mi & 1)*8 + mr) * 128
                                          + kb + (mi >> 1)*16);
                ldsm4(stb + 16384 + SW128(off), al[fm][0], al[fm][1], al[fm][2], al[fm][3]);
            }
            #pragma unroll
            for (int fm = 0; fm < 4; fm++)
                #pragma unroll
                for (int fn = 0; fn < 4; fn++)
                    mma_bf16(acc[fm][fn], al[fm], bh[fn]);
        }
        __syncthreads();
    }

    #pragma unroll
    for (int fm = 0; fm < 4; fm++) {
        #pragma unroll
        for (int fn = 0; fn < 4; fn++) {
            const int row0 = m0 + wm + fm*16 + (lane >> 2);
            const int col  = n0 + wn + fn*8 + (lane & 3)*2;
            #pragma unroll
            for (int half = 0; half < 2; half++) {
                const int row = row0 + half*8;
                #pragma unroll
                for (int e = 0; e < 2; e++) {
                    const int c = col + e;
                    float v = acc[fm][fn][half*2 + e] + bias[c];
                    if (QKV) {
                        const int b = row >> 11;
                        const int s = row & 2047;
                        const int which = c >> 10;
                        const int h = (c >> 6) & 15;
                        const int dd = c & 63;
                        __nv_bfloat16 vh = __float2bfloat16(v);
                        __nv_bfloat16 vl = __float2bfloat16(v - __bfloat162float(vh));
                        if (which == 2) {
                            const size_t o = ((size_t)((b*HH + h)*DD + dd))*SS + s;
                            g_Vhi[o] = vh; g_Vlo[o] = vl;
                        } else {
                            const size_t o = ((size_t)((b*HH + h)*SS + s))*DD + dd;
                            if (which == 0) { g_Qhi[o] = vh; g_Qlo[o] = vl; }
                            else            { g_Khi[o] = vh; g_Klo[o] = vl; }
                        }
                    } else {
                        C[(size_t)row * N + c] = v;
                    }
                }
            }
        }
    }
}

// ---------------------------------------------------------------------------
// HMMA bf16x3 flash attention, cp.async double-buffered.
// Dyn smem: 2 stages x 32KB (Khi|Klo|VhiT|VloT each 8KB) + 2 x 64 mask ints.
// ---------------------------------------------------------------------------
__global__ __launch_bounds__(256)
void attn_mma_kernel(const int* __restrict__ mask)
{
    extern __shared__ char smem[];
    const uint32_t sb = smem_u32(smem);
    int* mski = (int*)(smem + 65536);          // 2 stages x 64 ints

    const int bh = blockIdx.y;
    const int b  = bh >> 4;
    const int hh = bh & 15;
    const int q0 = blockIdx.x * 128;
    const int tid = threadIdx.x, wid = tid >> 5, lane = tid & 31;
    const int mi = lane >> 3, mr = lane & 7;

    // ---- stage Q tile (128x64 hi/lo) into stage0/1 region, pull frags
    {
        const __nv_bfloat16* qh = g_Qhi + ((size_t)bh*SS + q0)*DD;
        const __nv_bfloat16* ql = g_Qlo + ((size_t)bh*SS + q0)*DD;
        #pragma unroll
        for (int i = 0; i < 4; i++) {
            int idx = i*256 + tid;
            int row = idx >> 3, cg = idx & 7;
            uint32_t off = row*128 + cg*16;
            *(uint4*)(smem + SW128(off))         = *(const uint4*)(qh + (size_t)row*DD + cg*8);
            *(uint4*)(smem + 16384 + SW128(off)) = *(const uint4*)(ql + (size_t)row*DD + cg*8);
        }
    }
    __syncthreads();
    uint32_t qh[4][4], ql[4][4];
    #pragma unroll
    for (int kf = 0; kf < 4; kf++) {
        uint32_t off = (uint32_t)((wid*16 + (mi & 1)*8 + mr)*128 + kf*32 + (mi >> 1)*16);
        ldsm4(sb + SW128(off),         qh[kf][0], qh[kf][1], qh[kf][2], qh[kf][3]);
        ldsm4(sb + 16384 + SW128(off), ql[kf][0], ql[kf][1], ql[kf][2], ql[kf][3]);
    }
    __syncthreads();

    const __nv_bfloat16* Khi0 = g_Khi + (size_t)bh*SS*DD;
    const __nv_bfloat16* Klo0 = g_Klo + (size_t)bh*SS*DD;
    const __nv_bfloat16* Vhi0 = g_Vhi + (size_t)bh*DD*SS;
    const __nv_bfloat16* Vlo0 = g_Vlo + (size_t)bh*DD*SS;

    auto issue = [&](int kt, int st){
        const int k0 = kt*64;
        const uint32_t stb = sb + st*32768;
        #pragma unroll
        for (int i = 0; i < 2; i++) {
            int idx = i*256 + tid;
            int row = idx >> 3, cg = idx & 7;
            uint32_t swo = SW128((uint32_t)(row*128 + cg*16));
            cp_async16(stb + swo,         Khi0 + (size_t)(k0+row)*DD + cg*8);
            cp_async16(stb + 8192 + swo,  Klo0 + (size_t)(k0+row)*DD + cg*8);
            cp_async16(stb + 16384 + swo, Vhi0 + (size_t)row*SS + k0 + cg*8);
            cp_async16(stb + 24576 + swo, Vlo0 + (size_t)row*SS + k0 + cg*8);
        }
        if (tid < 16)
            cp_async16(sb + 65536 + st*256 + tid*16, mask + b*SS + k0 + tid*4);
        CP_COMMIT();
    };

    float O[8][4];
    #pragma unroll
    for (int fn = 0; fn < 8; fn++)
        #pragma unroll
        for (int r = 0; r < 4; r++) O[fn][r] = 0.0f;
    float m_prev[2] = {-1e30f, -1e30f}, l_prev[2] = {0.0f, 0.0f};

    issue(0, 0);

    const int NT = SS/64;
    for (int kt = 0; kt < NT; kt++) {
        const int st = kt & 1;
        if (kt + 1 < NT) { issue(kt + 1, st ^ 1); CP_WAIT(1); }
        else             { CP_WAIT(0); }
        __syncthreads();
        const uint32_t stb = sb + st*32768;
        const int* mst = mski + st*64;

        // ---- S = Q K^T (3-pass split)
        float S[8][4];
        #pragma unroll
        for (int fn = 0; fn < 8; fn++)
            #pragma unroll
            for (int r = 0; r < 4; r++) S[fn][r] = 0.0f;

        #pragma unroll
        for (int kf = 0; kf < 4; kf++) {
            uint32_t kh[8][2], kl[8][2];
            #pragma unroll
            for (int fn2 = 0; fn2 < 4; fn2++) {
                uint32_t off = (uint32_t)((fn2*16 + (mi >> 1)*8 + mr)*128 + kf*32 + (mi & 1)*16);
                ldsm4(stb + SW128(off),
                      kh[fn2*2][0], kh[fn2*2][1], kh[fn2*2+1][0], kh[fn2*2+1][1]);
                ldsm4(stb + 8192 + SW128(off),
                      kl[fn2*2][0], kl[fn2*2][1], kl[fn2*2+1][0], kl[fn2*2+1][1]);
            }
            #pragma unroll
            for (int fn = 0; fn < 8; fn++) {
                mma_bf16(S[fn], qh[kf], kh[fn]);
                mma_bf16(S[fn], qh[kf], kl[fn]);
                mma_bf16(S[fn], ql[kf], kh[fn]);
            }
        }

        // ---- mask + scale
        #pragma unroll
        for (int fn = 0; fn < 8; fn++) {
            const int c0 = fn*8 + (lane & 3)*2;
            const float b0 = mst[c0]   ? 0.0f : -1e30f;
            const float b1 = mst[c0+1] ? 0.0f : -1e30f;
            S[fn][0] = S[fn][0]*0.125f + b0;
            S[fn][1] = S[fn][1]*0.125f + b1;
            S[fn][2] = S[fn][2]*0.125f + b0;
            S[fn][3] = S[fn][3]*0.125f + b1;
        }

        // ---- online softmax
        float mnew[2], alpha[2];
        #pragma unroll
        for (int h = 0; h < 2; h++) {
            float mx = -1e30f;
            #pragma unroll
            for (int fn = 0; fn < 8; fn++)
                mx = fmaxf(mx, fmaxf(S[fn][h*2], S[fn][h*2+1]));
            mx = fmaxf(mx, __shfl_xor_sync(0xffffffffu, mx, 1));
            mx = fmaxf(mx, __shfl_xor_sync(0xffffffffu, mx, 2));
            mnew[h] = fmaxf(m_prev[h], mx);
            alpha[h] = __expf(m_prev[h] - mnew[h]);
            m_prev[h] = mnew[h];
        }
        float ls[2] = {0.0f, 0.0f};
        #pragma unroll
        for (int fn = 0; fn < 8; fn++) {
            #pragma unroll
            for (int h = 0; h < 2; h++) {
                S[fn][h*2]   = __expf(S[fn][h*2]   - mnew[h]);
                S[fn][h*2+1] = __expf(S[fn][h*2+1] - mnew[h]);
                ls[h] += S[fn][h*2] + S[fn][h*2+1];
            }
        }
        #pragma unroll
        for (int h = 0; h < 2; h++) {
            ls[h] += __shfl_xor_sync(0xffffffffu, ls[h], 1);
            ls[h] += __shfl_xor_sync(0xffffffffu, ls[h], 2);
            l_prev[h] = l_prev[h]*alpha[h] + ls[h];
        }
        #pragma unroll
        for (int fn = 0; fn < 8; fn++) {
            O[fn][0] *= alpha[0]; O[fn][1] *= alpha[0];
            O[fn][2] *= alpha[1]; O[fn][3] *= alpha[1];
        }

        // ---- O += P V (3-pass split)
        #pragma unroll
        for (int kf = 0; kf < 4; kf++) {
            uint32_t phi[4], plo[4];
            {
                const float* s0 = S[2*kf];
                const float* s1 = S[2*kf + 1];
                float r[8] = {s0[0], s0[1], s0[2], s0[3], s1[0], s1[1], s1[2], s1[3]};
                float h[8], l[8];
                #pragma unroll
                for (int e = 0; e < 8; e++) {
                    __nv_bfloat16 t = __float2bfloat16(r[e]);
                    h[e] = __bfloat162float(t);
                    l[e] = r[e] - h[e];
                }
                phi[0] = pack_bf16(h[0], h[1]); phi[1] = pack_bf16(h[2], h[3]);
                phi[2] = pack_bf16(h[4], h[5]); phi[3] = pack_bf16(h[6], h[7]);
                plo[0] = pack_bf16(l[0], l[1]); plo[1] = pack_bf16(l[2], l[3]);
                plo[2] = pack_bf16(l[4], l[5]); plo[3] = pack_bf16(l[6], l[7]);
            }
            uint32_t vh[8][2], vl[8][2];
            #pragma unroll
            for (int fn2 = 0; fn2 < 4; fn2++) {
                uint32_t off = (uint32_t)((fn2*16 + (mi >> 1)*8 + mr)*128 + kf*32 + (mi & 1)*16);
                ldsm4(stb + 16384 + SW128(off),
                      vh[fn2*2][0], vh[fn2*2][1], vh[fn2*2+1][0], vh[fn2*2+1][1]);
                ldsm4(stb + 24576 + SW128(off),
                      vl[fn2*2][0], vl[fn2*2][1], vl[fn2*2+1][0], vl[fn2*2+1][1]);
            }
            #pragma unroll
            for (int fn = 0; fn < 8; fn++) {
                mma_bf16(O[fn], phi, vh[fn]);
                mma_bf16(O[fn], phi, vl[fn]);
                mma_bf16(O[fn], plo, vh[fn]);
            }
        }
        __syncthreads();
    }

    // ---- epilogue: write ctx directly as bf16 hi/lo (fused split)
    const float inv0 = 1.0f / l_prev[0];
    const float inv1 = 1.0f / l_prev[1];
    const int row0 = q0 + wid*16 + (lane >> 2);
    #pragma unroll
    for (int fn = 0; fn < 8; fn++) {
        const int dcol = fn*8 + (lane & 3)*2;
        const size_t o0 = (size_t)(b*SS + row0)*EE + hh*DD + dcol;
        const size_t o1 = (size_t)(b*SS + row0 + 8)*EE + hh*DD + dcol;
        float v00 = O[fn][0]*inv0, v01 = O[fn][1]*inv0;
        float v10 = O[fn][2]*inv1, v11 = O[fn][3]*inv1;
        __nv_bfloat16 h;
        h = __float2bfloat16(v00); g_cthi[o0]   = h; g_ctlo[o0]   = __float2bfloat16(v00 - __bfloat162float(h));
        h = __float2bfloat16(v01); g_cthi[o0+1] = h; g_ctlo[o0+1] = __float2bfloat16(v01 - __bfloat162float(h));
        h = __float2bfloat16(v10); g_cthi[o1]   = h; g_ctlo[o1]   = __float2bfloat16(v10 - __bfloat162float(h));
        h = __float2bfloat16(v11); g_cthi[o1+1] = h; g_ctlo[o1+1] = __float2bfloat16(v11 - __bfloat162float(h));
    }
}

// ---------------------------------------------------------------------------
extern "C" void kernel_launch(void* const* d_in, const int* in_sizes, int n_in,
                              void* d_out, int out_size)
{
    const float* x    = (const float*)d_in[0];
    const int*   mask = (const int*)  d_in[1];
    const float* Wqkv = (const float*)d_in[2];
    const float* bqkv = (const float*)d_in[3];
    const float* Wout = (const float*)d_in[4];
    const float* bout = (const float*)d_in[5];
    float* out = (float*)d_out;

    __nv_bfloat16 *xhi, *xlo, *cthi, *ctlo, *wqhi, *wqlo, *wohi, *wolo;
    cudaGetSymbolAddress((void**)&xhi,  g_xhi);
    cudaGetSymbolAddress((void**)&xlo,  g_xlo);
    cudaGetSymbolAddress((void**)&cthi, g_cthi);
    cudaGetSymbolAddress((void**)&ctlo, g_ctlo);
    cudaGetSymbolAddress((void**)&wqhi, g_wqhi);
    cudaGetSymbolAddress((void**)&wqlo, g_wqlo);
    cudaGetSymbolAddress((void**)&wohi, g_wohi);
    cudaGetSymbolAddress((void**)&wolo, g_wolo);

    const int gemm_smem = 2 * 65536;      // 128KB
    const int attn_smem = 65536 + 512;    // 64KB + mask
    cudaFuncSetAttribute(gemm_mma_kernel<3*EE, true>,
                         cudaFuncAttributeMaxDynamicSharedMemorySize, gemm_smem);
    cudaFuncSetAttribute(gemm_mma_kernel<EE, false>,
                         cudaFuncAttributeMaxDynamicSharedMemorySize, gemm_smem);
    cudaFuncSetAttribute(attn_mma_kernel,
                         cudaFuncAttributeMaxDynamicSharedMemorySize, attn_smem);

    // prep
    split_kernel<<<ROWS*KK/4/256, 256>>>(x, xhi, xlo, ROWS*KK/4);
    transpose_split_kernel<<<dim3(3*EE/32, KK/32), 256>>>(Wqkv, wqhi, wqlo, KK, 3*EE);
    transpose_split_kernel<<<dim3(EE/32, KK/32), 256>>>(Wout, wohi, wolo, KK, EE);

    // 1) QKV projection (HMMA, pipelined) + split/scatter epilogue
    gemm_mma_kernel<3*EE, true><<<dim3(3*EE/128, ROWS/128), 256, gemm_smem>>>(
        xhi, xlo, wqhi, wqlo, bqkv, nullptr);

    // 2) attention (HMMA bf16x3 flash, pipelined)
    attn_mma_kernel<<<dim3(SS/128, BB*HH), 256, attn_smem>>>(mask);

    // 3) output projection (HMMA, pipelined)
    gemm_mma_kernel<EE, false><<<dim3(EE/128, ROWS/128), 256, gemm_smem>>>(
        cthi, ctlo, wohi, wolo, bout, out);
}

// round 7
// speedup vs baseline: 3.6139x; 1.0161x over previous
#include <cuda_runtime.h>
#include <cuda_bf16.h>
#include <math.h>
#include <stdint.h>

#define BB 2
#define SS 2048
#define EE 1024
#define HH 16
#define DD 64
#define ROWS (BB*SS)     // 4096
#define KK 1024

// ---------------- scratch (device globals; no allocation) -------------------
__device__ __nv_bfloat16 g_Qhi[BB*HH*SS*DD], g_Qlo[BB*HH*SS*DD];   // [bh][s][d]
__device__ __nv_bfloat16 g_Khi[BB*HH*SS*DD], g_Klo[BB*HH*SS*DD];   // [bh][s][d]
__device__ __nv_bfloat16 g_Vhi[BB*HH*SS*DD], g_Vlo[BB*HH*SS*DD];   // [bh][d][s]
__device__ __nv_bfloat16 g_xhi[ROWS*KK], g_xlo[ROWS*KK];
__device__ __nv_bfloat16 g_cthi[ROWS*KK], g_ctlo[ROWS*KK];
__device__ __nv_bfloat16 g_wqhi[3*EE*KK], g_wqlo[3*EE*KK];   // [N=3072][K]
__device__ __nv_bfloat16 g_wohi[EE*KK],  g_wolo[EE*KK];      // [N=1024][K]

// ---------------- helpers ---------------------------------------------------
__device__ __forceinline__ uint32_t smem_u32(const void* p){
    uint32_t a;
    asm("{ .reg .u64 t; cvta.to.shared.u64 t, %1; cvt.u32.u64 %0, t; }" : "=r"(a) : "l"(p));
    return a;
}
#define SW128(o) ((o) ^ (((o) >> 3) & 0x70))

__device__ __forceinline__ void ldsm4(uint32_t addr, uint32_t& r0, uint32_t& r1,
                                      uint32_t& r2, uint32_t& r3){
    asm volatile("ldmatrix.sync.aligned.m8n8.x4.shared.b16 {%0,%1,%2,%3}, [%4];"
        : "=r"(r0), "=r"(r1), "=r"(r2), "=r"(r3) : "r"(addr));
}
__device__ __forceinline__ void mma_bf16(float* c, const uint32_t* a, const uint32_t* b){
    asm volatile("mma.sync.aligned.m16n8k16.row.col.f32.bf16.bf16.f32 "
        "{%0,%1,%2,%3}, {%4,%5,%6,%7}, {%8,%9}, {%0,%1,%2,%3};"
        : "+f"(c[0]), "+f"(c[1]), "+f"(c[2]), "+f"(c[3])
        : "r"(a[0]), "r"(a[1]), "r"(a[2]), "r"(a[3]), "r"(b[0]), "r"(b[1]));
}
__device__ __forceinline__ uint32_t pack_bf16(float lo, float hi){
    __nv_bfloat162 t = __floats2bfloat162_rn(lo, hi);
    return *(uint32_t*)&t;
}
__device__ __forceinline__ void cp_async16(uint32_t saddr, const void* gptr){
    asm volatile("cp.async.cg.shared.global [%0], [%1], 16;" :: "r"(saddr), "l"(gptr));
}
#define CP_COMMIT() asm volatile("cp.async.commit_group;" ::: "memory")
#define CP_WAIT(N)  asm volatile("cp.async.wait_group %0;" :: "n"(N) : "memory")

// ---------------------------------------------------------------------------
// Prep kernels
// ---------------------------------------------------------------------------
__global__ __launch_bounds__(256)
void split_kernel(const float* __restrict__ src, __nv_bfloat16* __restrict__ hi,
                  __nv_bfloat16* __restrict__ lo, int n4)
{
    int i = blockIdx.x * 256 + threadIdx.x;
    if (i >= n4) return;
    float4 v = ((const float4*)src)[i];
    __nv_bfloat16 h[4], l[4];
    float f[4] = {v.x, v.y, v.z, v.w};
    #pragma unroll
    for (int j = 0; j < 4; j++) {
        h[j] = __float2bfloat16(f[j]);
        l[j] = __float2bfloat16(f[j] - __bfloat162float(h[j]));
    }
    ((__nv_bfloat162*)hi)[i*2+0] = __nv_bfloat162(h[0], h[1]);
    ((__nv_bfloat162*)hi)[i*2+1] = __nv_bfloat162(h[2], h[3]);
    ((__nv_bfloat162*)lo)[i*2+0] = __nv_bfloat162(l[0], l[1]);
    ((__nv_bfloat162*)lo)[i*2+1] = __nv_bfloat162(l[2], l[3]);
}

__global__ __launch_bounds__(256)
void transpose_split_kernel(const float* __restrict__ W, __nv_bfloat16* __restrict__ Thi,
                            __nv_bfloat16* __restrict__ Tlo, int K, int N)
{
    __shared__ float tile[32][33];
    const int n0 = blockIdx.x * 32, k0 = blockIdx.y * 32;
    const int tx = threadIdx.x & 31, ty = threadIdx.x >> 5;
    #pragma unroll
    for (int i = 0; i < 4; i++)
        tile[ty + 8*i][tx] = W[(size_t)(k0 + ty + 8*i) * N + n0 + tx];
    __syncthreads();
    #pragma unroll
    for (int i = 0; i < 4; i++) {
        float v = tile[tx][ty + 8*i];
        __nv_bfloat16 h = __float2bfloat16(v);
        size_t o = (size_t)(n0 + ty + 8*i) * K + k0 + tx;
        Thi[o] = h;
        Tlo[o] = __float2bfloat16(v - __bfloat162float(h));
    }
}

// ---------------------------------------------------------------------------
// HMMA bf16x3 GEMM, 3-stage cp.async pipeline.
// Dyn smem: 3 stages x (Ahi|Alo|Bhi|Blo each 16KB) = 192KB.
// ---------------------------------------------------------------------------
template<int N, bool QKV>
__global__ __launch_bounds__(256)
void gemm_mma_kernel(const __nv_bfloat16* __restrict__ Ahi, const __nv_bfloat16* __restrict__ Alo,
                     const __nv_bfloat16* __restrict__ Bhi, const __nv_bfloat16* __restrict__ Blo,
                     const float* __restrict__ bias, float* __restrict__ C)
{
    extern __shared__ char smem[];
    const uint32_t sb = smem_u32(smem);
    const int tid = threadIdx.x;
    const int wid = tid >> 5;
    const int lane = tid & 31;
    const int m0 = blockIdx.y * 128;
    const int n0 = blockIdx.x * 128;
    const int wm = (wid & 1) * 64;
    const int wn = (wid >> 1) * 32;
    const int mi = lane >> 3;
    const int mr = lane & 7;

    const __nv_bfloat16* srcs[4] = {Ahi, Alo, Bhi, Blo};
    const int rb[4] = {m0, m0, n0, n0};

    auto issue = [&](int chunk, int st){
        const int k0 = chunk * 64;
        const uint32_t stb = sb + st * 65536;
        #pragma unroll
        for (int t = 0; t < 4; t++) {
            #pragma unroll
            for (int i = 0; i < 4; i++) {
                const int idx = i * 256 + tid;
                const int row = idx >> 3;
                const int cg  = idx & 7;
                cp_async16(stb + t*16384 + SW128((uint32_t)(row*128 + cg*16)),
                           srcs[t] + (size_t)(rb[t] + row) * KK + k0 + cg * 8);
            }
        }
        CP_COMMIT();
    };

    float acc[4][4][4];
    #pragma unroll
    for (int i = 0; i < 4; i++)
        #pragma unroll
        for (int j = 0; j < 4; j++)
            #pragma unroll
            for (int r = 0; r < 4; r++) acc[i][j][r] = 0.0f;

    issue(0, 0);
    issue(1, 1);

    const int NC = KK/64;
    int st = 0;
    for (int chunk = 0; chunk < NC; chunk++) {
        CP_WAIT(1);
        __syncthreads();
        if (chunk + 2 < NC) {
            int st2 = st + 2; if (st2 >= 3) st2 -= 3;
            issue(chunk + 2, st2);
        }

        const uint32_t stb = sb + st * 65536;
        #pragma unroll
        for (int ks = 0; ks < 4; ks++) {
            const int kb = ks * 32;
            uint32_t ah[4][4], al[4][4], bh[4][2], bl[4][2];
            #pragma unroll
            for (int fm = 0; fm < 4; fm++) {
                uint32_t off = (uint32_t)((wm + fm*16 + (mi & 1)*8 + mr) * 128
                                          + kb + (mi >> 1)*16);
                ldsm4(stb + SW128(off), ah[fm][0], ah[fm][1], ah[fm][2], ah[fm][3]);
            }
            #pragma unroll
            for (int fn2 = 0; fn2 < 2; fn2++) {
                uint32_t off = (uint32_t)((wn + fn2*16 + (mi >> 1)*8 + mr) * 128
                                          + kb + (mi & 1)*16);
                ldsm4(stb + 32768 + SW128(off),
                      bh[fn2*2][0], bh[fn2*2][1], bh[fn2*2+1][0], bh[fn2*2+1][1]);
            }
            #pragma unroll
            for (int fm = 0; fm < 4; fm++)
                #pragma unroll
                for (int fn = 0; fn < 4; fn++)
                    mma_bf16(acc[fm][fn], ah[fm], bh[fn]);
            #pragma unroll
            for (int fn2 = 0; fn2 < 2; fn2++) {
                uint32_t off = (uint32_t)((wn + fn2*16 + (mi >> 1)*8 + mr) * 128
                                          + kb + (mi & 1)*16);
                ldsm4(stb + 49152 + SW128(off),
                      bl[fn2*2][0], bl[fn2*2][1], bl[fn2*2+1][0], bl[fn2*2+1][1]);
            }
            #pragma unroll
            for (int fm = 0; fm < 4; fm++)
                #pragma unroll
                for (int fn = 0; fn < 4; fn++)
                    mma_bf16(acc[fm][fn], ah[fm], bl[fn]);
            #pragma unroll
            for (int fm = 0; fm < 4; fm++) {
                uint32_t off = (uint32_t)((wm + fm*16 + (mi & 1)*8 + mr) * 128
                                          + kb + (mi >> 1)*16);
                ldsm4(stb + 16384 + SW128(off), al[fm][0], al[fm][1], al[fm][2], al[fm][3]);
            }
            #pragma unroll
            for (int fm = 0; fm < 4; fm++)
                #pragma unroll
                for (int fn = 0; fn < 4; fn++)
                    mma_bf16(acc[fm][fn], al[fm], bh[fn]);
        }
        if (++st >= 3) st = 0;
    }

    #pragma unroll
    for (int fm = 0; fm < 4; fm++) {
        #pragma unroll
        for (int fn = 0; fn < 4; fn++) {
            const int row0 = m0 + wm + fm*16 + (lane >> 2);
            const int col  = n0 + wn + fn*8 + (lane & 3)*2;
            #pragma unroll
            for (int half = 0; half < 2; half++) {
                const int row = row0 + half*8;
                #pragma unroll
                for (int e = 0; e < 2; e++) {
                    const int c = col + e;
                    float v = acc[fm][fn][half*2 + e] + bias[c];
                    if (QKV) {
                        const int b = row >> 11;
                        const int s = row & 2047;
                        const int which = c >> 10;
                        const int h = (c >> 6) & 15;
                        const int dd = c & 63;
                        __nv_bfloat16 vh = __float2bfloat16(v);
                        __nv_bfloat16 vl = __float2bfloat16(v - __bfloat162float(vh));
                        if (which == 2) {
                            const size_t o = ((size_t)((b*HH + h)*DD + dd))*SS + s;
                            g_Vhi[o] = vh; g_Vlo[o] = vl;
                        } else {
                            const size_t o = ((size_t)((b*HH + h)*SS + s))*DD + dd;
                            if (which == 0) { g_Qhi[o] = vh; g_Qlo[o] = vl; }
                            else            { g_Khi[o] = vh; g_Klo[o] = vl; }
                        }
                    } else {
                        C[(size_t)row * N + c] = v;
                    }
                }
            }
        }
    }
}

// ---------------------------------------------------------------------------
// HMMA bf16x3 flash attention, 3-stage cp.async pipeline.
// Dyn smem: 3 stages x 32KB (Khi|Klo|VhiT|VloT each 8KB) + 3 x 64 mask ints.
// ---------------------------------------------------------------------------
__global__ __launch_bounds__(256)
void attn_mma_kernel(const int* __restrict__ mask)
{
    extern __shared__ char smem[];
    const uint32_t sb = smem_u32(smem);
    int* mski = (int*)(smem + 98304);          // 3 stages x 64 ints

    const int bh = blockIdx.y;
    const int b  = bh >> 4;
    const int hh = bh & 15;
    const int q0 = blockIdx.x * 128;
    const int tid = threadIdx.x, wid = tid >> 5, lane = tid & 31;
    const int mi = lane >> 3, mr = lane & 7;

    // ---- stage Q tile (128x64 hi/lo), pull frags
    {
        const __nv_bfloat16* qh = g_Qhi + ((size_t)bh*SS + q0)*DD;
        const __nv_bfloat16* ql = g_Qlo + ((size_t)bh*SS + q0)*DD;
        #pragma unroll
        for (int i = 0; i < 4; i++) {
            int idx = i*256 + tid;
            int row = idx >> 3, cg = idx & 7;
            uint32_t off = row*128 + cg*16;
            *(uint4*)(smem + SW128(off))         = *(const uint4*)(qh + (size_t)row*DD + cg*8);
            *(uint4*)(smem + 16384 + SW128(off)) = *(const uint4*)(ql + (size_t)row*DD + cg*8);
        }
    }
    __syncthreads();
    uint32_t qh[4][4], ql[4][4];
    #pragma unroll
    for (int kf = 0; kf < 4; kf++) {
        uint32_t off = (uint32_t)((wid*16 + (mi & 1)*8 + mr)*128 + kf*32 + (mi >> 1)*16);
        ldsm4(sb + SW128(off),         qh[kf][0], qh[kf][1], qh[kf][2], qh[kf][3]);
        ldsm4(sb + 16384 + SW128(off), ql[kf][0], ql[kf][1], ql[kf][2], ql[kf][3]);
    }
    __syncthreads();

    const __nv_bfloat16* Khi0 = g_Khi + (size_t)bh*SS*DD;
    const __nv_bfloat16* Klo0 = g_Klo + (size_t)bh*SS*DD;
    const __nv_bfloat16* Vhi0 = g_Vhi + (size_t)bh*DD*SS;
    const __nv_bfloat16* Vlo0 = g_Vlo + (size_t)bh*DD*SS;

    auto issue = [&](int kt, int st){
        const int k0 = kt*64;
        const uint32_t stb = sb + st*32768;
        #pragma unroll
        for (int i = 0; i < 2; i++) {
            int idx = i*256 + tid;
            int row = idx >> 3, cg = idx & 7;
            uint32_t swo = SW128((uint32_t)(row*128 + cg*16));
            cp_async16(stb + swo,         Khi0 + (size_t)(k0+row)*DD + cg*8);
            cp_async16(stb + 8192 + swo,  Klo0 + (size_t)(k0+row)*DD + cg*8);
            cp_async16(stb + 16384 + swo, Vhi0 + (size_t)row*SS + k0 + cg*8);
            cp_async16(stb + 24576 + swo, Vlo0 + (size_t)row*SS + k0 + cg*8);
        }
        if (tid < 16)
            cp_async16(sb + 98304 + st*256 + tid*16, mask + b*SS + k0 + tid*4);
        CP_COMMIT();
    };

    float O[8][4];
    #pragma unroll
    for (int fn = 0; fn < 8; fn++)
        #pragma unroll
        for (int r = 0; r < 4; r++) O[fn][r] = 0.0f;
    float m_prev[2] = {-1e30f, -1e30f}, l_prev[2] = {0.0f, 0.0f};

    issue(0, 0);
    issue(1, 1);

    const int NT = SS/64;
    int st = 0;
    for (int kt = 0; kt < NT; kt++) {
        CP_WAIT(1);
        __syncthreads();
        if (kt + 2 < NT) {
            int st2 = st + 2; if (st2 >= 3) st2 -= 3;
            issue(kt + 2, st2);
        }
        const uint32_t stb = sb + st*32768;
        const int* mst = mski + st*64;

        // ---- S = Q K^T (3-pass split)
        float S[8][4];
        #pragma unroll
        for (int fn = 0; fn < 8; fn++)
            #pragma unroll
            for (int r = 0; r < 4; r++) S[fn][r] = 0.0f;

        #pragma unroll
        for (int kf = 0; kf < 4; kf++) {
            uint32_t kh[8][2], kl[8][2];
            #pragma unroll
            for (int fn2 = 0; fn2 < 4; fn2++) {
                uint32_t off = (uint32_t)((fn2*16 + (mi >> 1)*8 + mr)*128 + kf*32 + (mi & 1)*16);
                ldsm4(stb + SW128(off),
                      kh[fn2*2][0], kh[fn2*2][1], kh[fn2*2+1][0], kh[fn2*2+1][1]);
                ldsm4(stb + 8192 + SW128(off),
                      kl[fn2*2][0], kl[fn2*2][1], kl[fn2*2+1][0], kl[fn2*2+1][1]);
            }
            #pragma unroll
            for (int fn = 0; fn < 8; fn++) {
                mma_bf16(S[fn], qh[kf], kh[fn]);
                mma_bf16(S[fn], qh[kf], kl[fn]);
                mma_bf16(S[fn], ql[kf], kh[fn]);
            }
        }

        // ---- mask + scale
        #pragma unroll
        for (int fn = 0; fn < 8; fn++) {
            const int c0 = fn*8 + (lane & 3)*2;
            const float b0 = mst[c0]   ? 0.0f : -1e30f;
            const float b1 = mst[c0+1] ? 0.0f : -1e30f;
            S[fn][0] = S[fn][0]*0.125f + b0;
            S[fn][1] = S[fn][1]*0.125f + b1;
            S[fn][2] = S[fn][2]*0.125f + b0;
            S[fn][3] = S[fn][3]*0.125f + b1;
        }

        // ---- online softmax
        float mnew[2], alpha[2];
        #pragma unroll
        for (int h = 0; h < 2; h++) {
            float mx = -1e30f;
            #pragma unroll
            for (int fn = 0; fn < 8; fn++)
                mx = fmaxf(mx, fmaxf(S[fn][h*2], S[fn][h*2+1]));
            mx = fmaxf(mx, __shfl_xor_sync(0xffffffffu, mx, 1));
            mx = fmaxf(mx, __shfl_xor_sync(0xffffffffu, mx, 2));
            mnew[h] = fmaxf(m_prev[h], mx);
            alpha[h] = __expf(m_prev[h] - mnew[h]);
            m_prev[h] = mnew[h];
        }
        float ls[2] = {0.0f, 0.0f};
        #pragma unroll
        for (int fn = 0; fn < 8; fn++) {
            #pragma unroll
            for (int h = 0; h < 2; h++) {
                S[fn][h*2]   = __expf(S[fn][h*2]   - mnew[h]);
                S[fn][h*2+1] = __expf(S[fn][h*2+1] - mnew[h]);
                ls[h] += S[fn][h*2] + S[fn][h*2+1];
            }
        }
        #pragma unroll
        for (int h = 0; h < 2; h++) {
            ls[h] += __shfl_xor_sync(0xffffffffu, ls[h], 1);
            ls[h] += __shfl_xor_sync(0xffffffffu, ls[h], 2);
            l_prev[h] = l_prev[h]*alpha[h] + ls[h];
        }
        #pragma unroll
        for (int fn = 0; fn < 8; fn++) {
            O[fn][0] *= alpha[0]; O[fn][1] *= alpha[0];
            O[fn][2] *= alpha[1]; O[fn][3] *= alpha[1];
        }

        // ---- O += P V (3-pass split)
        #pragma unroll
        for (int kf = 0; kf < 4; kf++) {
            uint32_t phi[4], plo[4];
            {
                const float* s0 = S[2*kf];
                const float* s1 = S[2*kf + 1];
                float r[8] = {s0[0], s0[1], s0[2], s0[3], s1[0], s1[1], s1[2], s1[3]};
                float h[8], l[8];
                #pragma unroll
                for (int e = 0; e < 8; e++) {
                    __nv_bfloat16 t = __float2bfloat16(r[e]);
                    h[e] = __bfloat162float(t);
                    l[e] = r[e] - h[e];
                }
                phi[0] = pack_bf16(h[0], h[1]); phi[1] = pack_bf16(h[2], h[3]);
                phi[2] = pack_bf16(h[4], h[5]); phi[3] = pack_bf16(h[6], h[7]);
                plo[0] = pack_bf16(l[0], l[1]); plo[1] = pack_bf16(l[2], l[3]);
                plo[2] = pack_bf16(l[4], l[5]); plo[3] = pack_bf16(l[6], l[7]);
            }
            uint32_t vh[8][2], vl[8][2];
            #pragma unroll
            for (int fn2 = 0; fn2 < 4; fn2++) {
                uint32_t off = (uint32_t)((fn2*16 + (mi >> 1)*8 + mr)*128 + kf*32 + (mi & 1)*16);
                ldsm4(stb + 16384 + SW128(off),
                      vh[fn2*2][0], vh[fn2*2][1], vh[fn2*2+1][0], vh[fn2*2+1][1]);
                ldsm4(stb + 24576 + SW128(off),
                      vl[fn2*2][0], vl[fn2*2][1], vl[fn2*2+1][0], vl[fn2*2+1][1]);
            }
            #pragma unroll
            for (int fn = 0; fn < 8; fn++) {
                mma_bf16(O[fn], phi, vh[fn]);
                mma_bf16(O[fn], phi, vl[fn]);
                mma_bf16(O[fn], plo, vh[fn]);
            }
        }
        if (++st >= 3) st = 0;
    }

    // ---- epilogue: write ctx directly as bf16 hi/lo (fused split)
    const float inv0 = 1.0f / l_prev[0];
    const float inv1 = 1.0f / l_prev[1];
    const int row0 = q0 + wid*16 + (lane >> 2);
    #pragma unroll
    for (int fn = 0; fn < 8; fn++) {
        const int dcol = fn*8 + (lane & 3)*2;
        const size_t o0 = (size_t)(b*SS + row0)*EE + hh*DD + dcol;
        const size_t o1 = (size_t)(b*SS + row0 + 8)*EE + hh*DD + dcol;
        float v00 = O[fn][0]*inv0, v01 = O[fn][1]*inv0;
        float v10 = O[fn][2]*inv1, v11 = O[fn][3]*inv1;
        __nv_bfloat16 h;
        h = __float2bfloat16(v00); g_cthi[o0]   = h; g_ctlo[o0]   = __float2bfloat16(v00 - __bfloat162float(h));
        h = __float2bfloat16(v01); g_cthi[o0+1] = h; g_ctlo[o0+1] = __float2bfloat16(v01 - __bfloat162float(h));
        h = __float2bfloat16(v10); g_cthi[o1]   = h; g_ctlo[o1]   = __float2bfloat16(v10 - __bfloat162float(h));
        h = __float2bfloat16(v11); g_cthi[o1+1] = h; g_ctlo[o1+1] = __float2bfloat16(v11 - __bfloat162float(h));
    }
}

// ---------------------------------------------------------------------------
extern "C" void kernel_launch(void* const* d_in, const int* in_sizes, int n_in,
                              void* d_out, int out_size)
{
    const float* x    = (const float*)d_in[0];
    const int*   mask = (const int*)  d_in[1];
    const float* Wqkv = (const float*)d_in[2];
    const float* bqkv = (const float*)d_in[3];
    const float* Wout = (const float*)d_in[4];
    const float* bout = (const float*)d_in[5];
    float* out = (float*)d_out;

    __nv_bfloat16 *xhi, *xlo, *cthi, *ctlo, *wqhi, *wqlo, *wohi, *wolo;
    cudaGetSymbolAddress((void**)&xhi,  g_xhi);
    cudaGetSymbolAddress((void**)&xlo,  g_xlo);
    cudaGetSymbolAddress((void**)&cthi, g_cthi);
    cudaGetSymbolAddress((void**)&ctlo, g_ctlo);
    cudaGetSymbolAddress((void**)&wqhi, g_wqhi);
    cudaGetSymbolAddress((void**)&wqlo, g_wqlo);
    cudaGetSymbolAddress((void**)&wohi, g_wohi);
    cudaGetSymbolAddress((void**)&wolo, g_wolo);

    const int gemm_smem = 3 * 65536;          // 192KB
    const int attn_smem = 3 * 32768 + 768;    // 96KB + mask
    cudaFuncSetAttribute(gemm_mma_kernel<3*EE, true>,
                         cudaFuncAttributeMaxDynamicSharedMemorySize, gemm_smem);
    cudaFuncSetAttribute(gemm_mma_kernel<EE, false>,
                         cudaFuncAttributeMaxDynamicSharedMemorySize, gemm_smem);
    cudaFuncSetAttribute(attn_mma_kernel,
                         cudaFuncAttributeMaxDynamicSharedMemorySize, attn_smem);

    // prep
    split_kernel<<<ROWS*KK/4/256, 256>>>(x, xhi, xlo, ROWS*KK/4);
    transpose_split_kernel<<<dim3(3*EE/32, KK/32), 256>>>(Wqkv, wqhi, wqlo, KK, 3*EE);
    transpose_split_kernel<<<dim3(EE/32, KK/32), 256>>>(Wout, wohi, wolo, KK, EE);

    // 1) QKV projection (HMMA, 3-stage) + split/scatter epilogue
    gemm_mma_kernel<3*EE, true><<<dim3(3*EE/128, ROWS/128), 256, gemm_smem>>>(
        xhi, xlo, wqhi, wqlo, bqkv, nullptr);

    // 2) attention (HMMA bf16x3 flash, 3-stage)
    attn_mma_kernel<<<dim3(SS/128, BB*HH), 256, attn_smem>>>(mask);

    // 3) output projection (HMMA, 3-stage)
    gemm_mma_kernel<EE, false><<<dim3(EE/128, ROWS/128), 256, gemm_smem>>>(
        cthi, ctlo, wohi, wolo, bout, out);
}